// round 6
// baseline (speedup 1.0000x reference)
#include <cuda_runtime.h>
#include <math.h>

#define Bb 64
#define Ll 256
#define DIN 768
#define MEMD 300
#define Hh 6
#define TOPK 1024
#define NCc 3
#define NLAYERS 2
#define DKk 50
#define BL (Bb*Ll)   // 16384

// ---------------- scratch (device globals; no runtime allocation) ----------------
__device__ float g_q[BL*DIN];
__device__ float g_k[BL*DIN];
__device__ float g_scores[Bb*Hh*Ll*Ll];
__device__ float g_pattn[Bb*Ll*Ll];
__device__ float g_kth[Bb];
__device__ unsigned char g_adj[Bb*Ll*Ll];
__device__ float g_h[BL*MEMD];
__device__ float g_proj[BL*MEMD];
__device__ float g_cat[BL*MEMD];
__device__ float g_si[Bb*Hh*Ll];
__device__ float g_sj[Bb*Hh*Ll];
__device__ float g_wcat[NLAYERS*MEMD*MEMD];

// ---------------- packed fp32x2 FMA helpers ----------------
#define FFMA2(acc, a2, b2) \
  asm("fma.rn.f32x2 %0, %1, %2, %3;" : "=l"(acc) : "l"(a2), "l"(b2), "l"(acc))

__device__ __forceinline__ unsigned long long dup_f32(float x){
  unsigned long long r;
  asm("mov.b64 %0, {%1, %1};" : "=l"(r) : "f"(x));
  return r;
}
__device__ __forceinline__ float2 unpack2(unsigned long long v){
  float2 c;
  asm("mov.b64 {%0, %1}, %2;" : "=f"(c.x), "=f"(c.y) : "l"(v));
  return c;
}

// ---------------- tf32 helpers ----------------
__device__ __forceinline__ unsigned f2tf32(float x){
  unsigned r; asm("cvt.rna.tf32.f32 %0, %1;" : "=r"(r) : "f"(x)); return r;
}
__device__ __forceinline__ void cvt_hilo(float v, float& h, float& l){
  unsigned hu = f2tf32(v);
  float hf = __uint_as_float(hu);
  h = hf;
  l = __uint_as_float(f2tf32(v - hf));
}
__device__ __forceinline__ void mma_tf32(float* d, const unsigned* a, const unsigned* b){
  asm("mma.sync.aligned.m16n8k8.row.col.f32.tf32.tf32.f32 "
      "{%0,%1,%2,%3},{%4,%5,%6,%7},{%8,%9},{%0,%1,%2,%3};"
      : "+f"(d[0]), "+f"(d[1]), "+f"(d[2]), "+f"(d[3])
      : "r"(a[0]), "r"(a[1]), "r"(a[2]), "r"(a[3]), "r"(b[0]), "r"(b[1]));
}

// granule index for fragment-native packed smem.
// (g = k8-group 0/1, klow = k&3, x = m-or-n 0..127). One granule = float4
// {hi_k, lo_k, hi_{k+4}, lo_{k+4}}. Swizzle keeps frag loads & staging <=2-way.
__device__ __forceinline__ int gidx(int g, int klow, int x){
  return (((g*4 + klow) << 7) + x) ^ (klow << 1) ^ ((x >> 3) & 7);
}

#define TSTG 1024              // granules per stage (2*4*128)
#define TGEMM_SMEM (2*TSTG*16*2)   // 2 operands, 2 stages, 16B granules = 65536

// ---------------- reduction helpers ----------------
__device__ __forceinline__ float warpSum(float v){
  #pragma unroll
  for(int o=16;o;o>>=1) v += __shfl_xor_sync(0xffffffffu, v, o);
  return v;
}
__device__ __forceinline__ float blockSum256(float v, float* sh){
  v = warpSum(v);
  int w = threadIdx.x >> 5;
  if((threadIdx.x & 31) == 0) sh[w] = v;
  __syncthreads();
  if(threadIdx.x < 8){
    float x = sh[threadIdx.x];
    #pragma unroll
    for(int o=4;o;o>>=1) x += __shfl_xor_sync(0xffu, x, o);
    if(threadIdx.x==0) sh[0] = x;
  }
  __syncthreads();
  float r = sh[0];
  __syncthreads();
  return r;
}

// =====================================================================
// 3xTF32 GEMM, fragment-native packed smem. C = A[M,K] @ W[K,N] + bias.
// Block 128x128, BK=16, 8 warps (4x2), warp tile 32x64.
// =====================================================================
__global__ __launch_bounds__(256) void gemm_tf32x3(
    const float* __restrict__ A, const float* __restrict__ W,
    const float* __restrict__ bias, float* __restrict__ C,
    int M, int N, int K)
{
  extern __shared__ float4 smg[];
  float4* AB = smg;            // [2][TSTG]
  float4* WB = smg + 2*TSTG;   // [2][TSTG]

  int tid = threadIdx.x, lane = tid & 31, wid = tid >> 5;
  int wm = wid & 3, wn = wid >> 2;
  int row0 = blockIdx.y*128, col0 = blockIdx.x*128;
  int nStages = (K + 15) >> 4;

  float acc[2][8][4];
  #pragma unroll
  for(int i=0;i<2;i++)
    #pragma unroll
    for(int j=0;j<8;j++)
      #pragma unroll
      for(int t=0;t<4;t++) acc[i][j][t] = 0.f;

  float4 pa[2], pw[2];

  #define GLOAD(k0)                                                         \
    {                                                                       \
      _Pragma("unroll")                                                     \
      for(int i=0;i<2;i++){                                                 \
        int f = tid + i*256; int m = f>>2, kq = f&3;                        \
        int gk = (k0) + kq*4;                                               \
        pa[i] = (gk < K) ? *(const float4*)&A[(size_t)(row0+m)*K + gk]      \
                         : make_float4(0.f,0.f,0.f,0.f);                    \
      }                                                                     \
      _Pragma("unroll")                                                     \
      for(int i=0;i<2;i++){                                                 \
        int f = tid + i*256; int kk = f>>5, n4 = f&31;                      \
        int gk = (k0) + kk, gc = col0 + n4*4;                               \
        pw[i] = (gk < K && gc < N) ? *(const float4*)&W[(size_t)gk*N + gc]  \
                                   : make_float4(0.f,0.f,0.f,0.f);          \
      }                                                                     \
    }

  #define SSTORE(p)                                                         \
    {                                                                       \
      float2* Ab2 = (float2*)(AB + (p)*TSTG);                               \
      float2* Wb2 = (float2*)(WB + (p)*TSTG);                               \
      _Pragma("unroll")                                                     \
      for(int i=0;i<2;i++){                                                 \
        int f = tid + i*256; int m = f>>2, kq = f&3;                        \
        int g = kq>>1, khalf = kq&1;                                        \
        float hv, lv;                                                       \
        cvt_hilo(pa[i].x, hv, lv); Ab2[gidx(g,0,m)*2+khalf] = make_float2(hv,lv); \
        cvt_hilo(pa[i].y, hv, lv); Ab2[gidx(g,1,m)*2+khalf] = make_float2(hv,lv); \
        cvt_hilo(pa[i].z, hv, lv); Ab2[gidx(g,2,m)*2+khalf] = make_float2(hv,lv); \
        cvt_hilo(pa[i].w, hv, lv); Ab2[gidx(g,3,m)*2+khalf] = make_float2(hv,lv); \
      }                                                                     \
      _Pragma("unroll")                                                     \
      for(int i=0;i<2;i++){                                                 \
        int f = tid + i*256; int kk = f>>5, n4 = f&31;                      \
        int g = kk>>3, klow = kk&3, khalf = (kk>>2)&1;                      \
        float hv, lv;                                                       \
        cvt_hilo(pw[i].x, hv, lv); Wb2[gidx(g,klow,n4*4+0)*2+khalf] = make_float2(hv,lv); \
        cvt_hilo(pw[i].y, hv, lv); Wb2[gidx(g,klow,n4*4+1)*2+khalf] = make_float2(hv,lv); \
        cvt_hilo(pw[i].z, hv, lv); Wb2[gidx(g,klow,n4*4+2)*2+khalf] = make_float2(hv,lv); \
        cvt_hilo(pw[i].w, hv, lv); Wb2[gidx(g,klow,n4*4+3)*2+khalf] = make_float2(hv,lv); \
      }                                                                     \
    }

  GLOAD(0);
  SSTORE(0);
  __syncthreads();

  int klow = lane & 3, quad = lane >> 2;

  for(int s=0; s<nStages; s++){
    int p = s & 1;
    if(s+1 < nStages) GLOAD((s+1)*16);

    const float4* Ap = AB + p*TSTG;
    const float4* Wp = WB + p*TSTG;

    #pragma unroll
    for(int g=0; g<2; g++){
      unsigned ah[2][4], al[2][4];
      #pragma unroll
      for(int mt=0; mt<2; mt++){
        int r = wm*32 + mt*16 + quad;
        float4 va = Ap[gidx(g, klow, r)];
        float4 vb = Ap[gidx(g, klow, r+8)];
        ah[mt][0]=__float_as_uint(va.x); ah[mt][1]=__float_as_uint(vb.x);
        ah[mt][2]=__float_as_uint(va.z); ah[mt][3]=__float_as_uint(vb.z);
        al[mt][0]=__float_as_uint(va.y); al[mt][1]=__float_as_uint(vb.y);
        al[mt][2]=__float_as_uint(va.w); al[mt][3]=__float_as_uint(vb.w);
      }
      #pragma unroll
      for(int nt=0; nt<8; nt++){
        int n = wn*64 + nt*8 + quad;
        float4 wv = Wp[gidx(g, klow, n)];
        unsigned bh[2] = {__float_as_uint(wv.x), __float_as_uint(wv.z)};
        unsigned bl[2] = {__float_as_uint(wv.y), __float_as_uint(wv.w)};
        #pragma unroll
        for(int mt=0; mt<2; mt++){
          mma_tf32(acc[mt][nt], ah[mt], bh);
          mma_tf32(acc[mt][nt], ah[mt], bl);
          mma_tf32(acc[mt][nt], al[mt], bh);
        }
      }
    }

    if(s+1 < nStages){
      SSTORE((s+1)&1);
      __syncthreads();
    }
  }

  #pragma unroll
  for(int mt=0; mt<2; mt++){
    int r0 = row0 + wm*32 + mt*16 + quad;
    #pragma unroll
    for(int nt=0; nt<8; nt++){
      int c = col0 + wn*64 + nt*8 + klow*2;
      if(c < N){
        float2 bs = *(const float2*)&bias[c];
        float2 o0; o0.x = acc[mt][nt][0] + bs.x; o0.y = acc[mt][nt][1] + bs.y;
        *(float2*)&C[(size_t)r0*N + c] = o0;
        float2 o1; o1.x = acc[mt][nt][2] + bs.x; o1.y = acc[mt][nt][3] + bs.y;
        *(float2*)&C[(size_t)(r0+8)*N + c] = o1;
      }
    }
  }
  #undef GLOAD
  #undef SSTORE
}

// =====================================================================
// QK^T scores, 3xTF32, NT: both operands row-major x k. K=128 exact.
// scores[bh][l][m] = (q_h[l,:] . k_h[m,:]) / sqrt(128)
// =====================================================================
__global__ __launch_bounds__(256) void qk_scores_tf32(
    const float* __restrict__ q, const float* __restrict__ k,
    float* __restrict__ scores)
{
  extern __shared__ float4 smg[];
  float4* AB = smg;
  float4* WB = smg + 2*TSTG;

  int bh = blockIdx.z;
  int b = bh / Hh, h = bh - b*Hh;
  const float* Ag = q + (size_t)b*Ll*DIN + (size_t)h*128;
  const float* Bg = k + (size_t)b*Ll*DIN + (size_t)h*128;

  int tid = threadIdx.x, lane = tid & 31, wid = tid >> 5;
  int wm = wid & 3, wn = wid >> 2;
  int row0 = blockIdx.y*128, col0 = blockIdx.x*128;
  const int nStages = 8;  // K=128

  float acc[2][8][4];
  #pragma unroll
  for(int i=0;i<2;i++)
    #pragma unroll
    for(int j=0;j<8;j++)
      #pragma unroll
      for(int t=0;t<4;t++) acc[i][j][t] = 0.f;

  float4 pa[2], pb[2];

  #define QGLOAD(k0)                                                        \
    {                                                                       \
      _Pragma("unroll")                                                     \
      for(int i=0;i<2;i++){                                                 \
        int f = tid + i*256; int m = f>>2, kq = f&3;                        \
        pa[i] = *(const float4*)&Ag[(size_t)(row0+m)*DIN + (k0) + kq*4];    \
        pb[i] = *(const float4*)&Bg[(size_t)(col0+m)*DIN + (k0) + kq*4];    \
      }                                                                     \
    }

  #define QSSTORE(p)                                                       \
    {                                                                      \
      float2* Ab2 = (float2*)(AB + (p)*TSTG);                              \
      float2* Bb2 = (float2*)(WB + (p)*TSTG);                              \
      _Pragma("unroll")                                                    \
      for(int i=0;i<2;i++){                                                \
        int f = tid + i*256; int m = f>>2, kq = f&3;                       \
        int g = kq>>1, khalf = kq&1;                                       \
        float hv, lv;                                                      \
        cvt_hilo(pa[i].x, hv, lv); Ab2[gidx(g,0,m)*2+khalf] = make_float2(hv,lv); \
        cvt_hilo(pa[i].y, hv, lv); Ab2[gidx(g,1,m)*2+khalf] = make_float2(hv,lv); \
        cvt_hilo(pa[i].z, hv, lv); Ab2[gidx(g,2,m)*2+khalf] = make_float2(hv,lv); \
        cvt_hilo(pa[i].w, hv, lv); Ab2[gidx(g,3,m)*2+khalf] = make_float2(hv,lv); \
        cvt_hilo(pb[i].x, hv, lv); Bb2[gidx(g,0,m)*2+khalf] = make_float2(hv,lv); \
        cvt_hilo(pb[i].y, hv, lv); Bb2[gidx(g,1,m)*2+khalf] = make_float2(hv,lv); \
        cvt_hilo(pb[i].z, hv, lv); Bb2[gidx(g,2,m)*2+khalf] = make_float2(hv,lv); \
        cvt_hilo(pb[i].w, hv, lv); Bb2[gidx(g,3,m)*2+khalf] = make_float2(hv,lv); \
      }                                                                    \
    }

  QGLOAD(0);
  QSSTORE(0);
  __syncthreads();

  int klow = lane & 3, quad = lane >> 2;

  for(int s=0; s<nStages; s++){
    int p = s & 1;
    if(s+1 < nStages) QGLOAD((s+1)*16);

    const float4* Ap = AB + p*TSTG;
    const float4* Bp = WB + p*TSTG;

    #pragma unroll
    for(int g=0; g<2; g++){
      unsigned ah[2][4], al[2][4];
      #pragma unroll
      for(int mt=0; mt<2; mt++){
        int r = wm*32 + mt*16 + quad;
        float4 va = Ap[gidx(g, klow, r)];
        float4 vb = Ap[gidx(g, klow, r+8)];
        ah[mt][0]=__float_as_uint(va.x); ah[mt][1]=__float_as_uint(vb.x);
        ah[mt][2]=__float_as_uint(va.z); ah[mt][3]=__float_as_uint(vb.z);
        al[mt][0]=__float_as_uint(va.y); al[mt][1]=__float_as_uint(vb.y);
        al[mt][2]=__float_as_uint(va.w); al[mt][3]=__float_as_uint(vb.w);
      }
      #pragma unroll
      for(int nt=0; nt<8; nt++){
        int n = wn*64 + nt*8 + quad;
        float4 wv = Bp[gidx(g, klow, n)];
        unsigned bhf[2] = {__float_as_uint(wv.x), __float_as_uint(wv.z)};
        unsigned blf[2] = {__float_as_uint(wv.y), __float_as_uint(wv.w)};
        #pragma unroll
        for(int mt=0; mt<2; mt++){
          mma_tf32(acc[mt][nt], ah[mt], bhf);
          mma_tf32(acc[mt][nt], ah[mt], blf);
          mma_tf32(acc[mt][nt], al[mt], bhf);
        }
      }
    }

    if(s+1 < nStages){
      QSSTORE((s+1)&1);
      __syncthreads();
    }
  }

  const float scale = 0.08838834764831845f; // 1/sqrt(128)
  #pragma unroll
  for(int mt=0; mt<2; mt++){
    int r0 = row0 + wm*32 + mt*16 + quad;
    #pragma unroll
    for(int nt=0; nt<8; nt++){
      int c = col0 + wn*64 + nt*8 + klow*2;
      float2 o0; o0.x = acc[mt][nt][0]*scale; o0.y = acc[mt][nt][1]*scale;
      *(float2*)&scores[((size_t)bh*Ll + r0)*Ll + c] = o0;
      float2 o1; o1.x = acc[mt][nt][2]*scale; o1.y = acc[mt][nt][3]*scale;
      *(float2*)&scores[((size_t)bh*Ll + r0 + 8)*Ll + c] = o1;
    }
  }
  #undef QGLOAD
  #undef QSSTORE
}

// ---------------- softmax over m per (b,l), all 6 heads batched ----------------
__global__ __launch_bounds__(256) void softmax_mean_kernel(
    const float* __restrict__ scores, float* __restrict__ pattn)
{
  __shared__ float red1[Hh][8];
  __shared__ float r1[Hh];
  __shared__ float red2[Hh][8];
  __shared__ float r2[Hh];
  int bl = blockIdx.x;
  int b = bl >> 8, l = bl & 255;
  int m = threadIdx.x, w = m >> 5, lane = m & 31;
  const float* base = scores + ((size_t)(b*Hh)*Ll + l)*Ll + m;
  float s[Hh];
  #pragma unroll
  for(int h=0;h<Hh;h++) s[h] = base[(size_t)h*Ll*Ll];

  float v[Hh];
  #pragma unroll
  for(int h=0;h<Hh;h++){
    v[h] = s[h];
    #pragma unroll
    for(int o=16;o;o>>=1) v[h] = fmaxf(v[h], __shfl_xor_sync(0xffffffffu, v[h], o));
  }
  if(lane == 0){
    #pragma unroll
    for(int h=0;h<Hh;h++) red1[h][w] = v[h];
  }
  __syncthreads();
  if(m < Hh){
    float x = red1[m][0];
    #pragma unroll
    for(int j=1;j<8;j++) x = fmaxf(x, red1[m][j]);
    r1[m] = x;
  }
  __syncthreads();

  float e[Hh];
  #pragma unroll
  for(int h=0;h<Hh;h++){
    e[h] = expf(s[h] - r1[h]);
    v[h] = e[h];
    #pragma unroll
    for(int o=16;o;o>>=1) v[h] += __shfl_xor_sync(0xffffffffu, v[h], o);
  }
  if(lane == 0){
    #pragma unroll
    for(int h=0;h<Hh;h++) red2[h][w] = v[h];
  }
  __syncthreads();
  if(m < Hh){
    float x = red2[m][0];
    #pragma unroll
    for(int j=1;j<8;j++) x += red2[m][j];
    r2[m] = x;
  }
  __syncthreads();

  float acc = 0.f;
  #pragma unroll
  for(int h=0;h<Hh;h++) acc += e[h] / r2[h];
  pattn[(size_t)bl*Ll + m] = acc * (1.f/6.f);
}

// ---------------- exact 1024th-largest per batch via radix select ----------------
__global__ __launch_bounds__(1024) void topk_select_kernel(
    const float* __restrict__ pattn, float* __restrict__ kth)
{
  int b = blockIdx.x;
  int tid = threadIdx.x;
  const unsigned* v = (const unsigned*)(pattn + (size_t)b*Ll*Ll);
  __shared__ unsigned hist[256];
  __shared__ unsigned s_prefix;
  __shared__ int s_k;
  if(tid == 0){ s_prefix = 0u; s_k = TOPK; }
  __syncthreads();
  for(int pass=3; pass>=0; --pass){
    int shift = pass*8;
    if(tid < 256) hist[tid] = 0u;
    __syncthreads();
    unsigned prefix = s_prefix;
    unsigned mask = (pass==3) ? 0u : (0xFFFFFFFFu << ((pass+1)*8));
    for(int i=tid; i<Ll*Ll; i+=1024){
      unsigned x = v[i];
      if((x & mask) == prefix) atomicAdd(&hist[(x >> shift) & 0xFF], 1u);
    }
    __syncthreads();
    if(tid == 0){
      int k = s_k, cum = 0;
      unsigned byte = 0;
      for(int bb=255; bb>=0; --bb){
        int c = (int)hist[bb];
        if(cum + c >= k){ byte = (unsigned)bb; s_k = k - cum; break; }
        cum += c;
      }
      s_prefix = prefix | (byte << shift);
    }
    __syncthreads();
  }
  if(tid == 0) kth[b] = __uint_as_float(s_prefix);
}

// ---------------- adjacency mask: diag | sel | sel^T ----------------
__global__ __launch_bounds__(256) void build_adj_kernel(
    const float* __restrict__ pattn, const float* __restrict__ kth,
    unsigned char* __restrict__ adj)
{
  int b = blockIdx.x >> 8, i = blockIdx.x & 255, j = threadIdx.x;
  float t = kth[b];
  const float* p = pattn + (size_t)b*Ll*Ll;
  bool e = (i==j) || (p[(size_t)i*Ll + j] >= t) || (p[(size_t)j*Ll + i] >= t);
  adj[(size_t)b*Ll*Ll + (size_t)i*Ll + j] = e ? 1 : 0;
}

// ---------------- repack Wh(layer,h,d,k) -> Wcat(layer, d, h*50+k) ----------------
__global__ void repack_wh_kernel(const float* __restrict__ Wh, float* __restrict__ wcat){
  int idx = blockIdx.x*blockDim.x + threadIdx.x;
  if(idx >= NLAYERS*Hh*MEMD*DKk) return;
  int layer = idx / (Hh*MEMD*DKk);
  int r = idx - layer*(Hh*MEMD*DKk);
  int h = r / (MEMD*DKk);
  int r2 = r - h*(MEMD*DKk);
  int d = r2 / DKk;
  int kk = r2 - d*DKk;
  wcat[(size_t)layer*MEMD*MEMD + (size_t)d*MEMD + h*DKk + kk] = Wh[idx];
}

// ---------------- s_i, s_j per (b,h,l) ----------------
__global__ void sisj_kernel(const float* __restrict__ proj, const float* __restrict__ awl,
                            float* __restrict__ si, float* __restrict__ sj)
{
  int idx = blockIdx.x*blockDim.x + threadIdx.x;
  if(idx >= Bb*Hh*Ll) return;
  int b = idx / (Hh*Ll);
  int r = idx - b*(Hh*Ll);
  int h = r / Ll;
  int l = r - h*Ll;
  const float* pr = proj + (((size_t)(b*Ll + l))*Hh + h)*DKk;
  const float* w1 = awl;
  const float* w2 = awl + DKk;
  float a = 0.f, c = 0.f;
  #pragma unroll
  for(int k2=0;k2<DKk;k2++){ float pv = pr[k2]; a = fmaf(pv, w1[k2], a); c = fmaf(pv, w2[k2], c); }
  si[idx] = a; sj[idx] = c;
}

// =====================================================================
// fused GAT attention: block per (b,h,half). Two-phase chunked.
// =====================================================================
__global__ __launch_bounds__(256) void gat_attn_kernel(
    const float* __restrict__ proj, const float* __restrict__ si, const float* __restrict__ sj,
    const unsigned char* __restrict__ adj, const float* __restrict__ abp,
    float* __restrict__ cat)
{
  extern __shared__ float smx[];
  float* projS = smx;
  float* Psm   = projS + Ll*DKk;
  float* sjS   = Psm + 32*Ll;
  float* siS   = sjS + Ll;

  int bhh = blockIdx.x;
  int bh = bhh >> 1, half = bhh & 1;
  int b = bh / Hh, h = bh - b*Hh;
  int tid = threadIdx.x;
  int lane = tid & 31, w = tid >> 5;

  {
    const float* projBase = proj + ((size_t)(b*Ll))*MEMD + h*DKk;
    float2* dst = (float2*)projS;
    for(int e=tid; e<Ll*25; e+=256){
      int m = e / 25, t = e - m*25;
      dst[m*25+t] = ((const float2*)(projBase + (size_t)m*MEMD))[t];
    }
  }
  sjS[tid] = sj[(size_t)bh*Ll + tid];
  if(tid < 128) siS[tid] = si[(size_t)bh*Ll + half*128 + tid];
  __syncthreads();

  float abv = abp[0];
  const unsigned char* adjb = adj + (size_t)b*Ll*Ll;

  for(int c=0; c<4; c++){
    #pragma unroll
    for(int rr=0; rr<4; rr++){
      int pr = w*4 + rr;
      int l = half*128 + c*32 + pr;
      float si_l = siS[c*32 + pr];
      const unsigned char* arow = adjb + (size_t)l*Ll;
      float pv[8]; bool okv[8];
      float mx = -3.0e38f;
      #pragma unroll
      for(int j=0;j<8;j++){
        int m = lane + j*32;
        float sval = si_l + sjS[m] + abv;
        sval = (sval > 0.f) ? sval : 0.2f*sval;
        bool ok = arow[m] != 0;
        okv[j] = ok; pv[j] = sval;
        mx = fmaxf(mx, ok ? sval : -3.0e38f);
      }
      #pragma unroll
      for(int o=16;o;o>>=1) mx = fmaxf(mx, __shfl_xor_sync(0xffffffffu, mx, o));
      float ev[8];
      float s = 0.f;
      #pragma unroll
      for(int j=0;j<8;j++){
        ev[j] = okv[j] ? expf(pv[j] - mx) : 0.f;
        s += ev[j];
      }
      #pragma unroll
      for(int o=16;o;o>>=1) s += __shfl_xor_sync(0xffffffffu, s, o);
      float inv = 1.0f / s;
      #pragma unroll
      for(int j=0;j<8;j++)
        Psm[pr*Ll + lane + j*32] = ev[j] * inv;
    }
    __syncthreads();

    if(lane < 25){
      unsigned long long acc[4] = {0ull,0ull,0ull,0ull};
      const unsigned long long* Vp = (const unsigned long long*)projS;
      #pragma unroll 4
      for(int m=0; m<Ll; m++){
        unsigned long long bv = Vp[m*25 + lane];
        #pragma unroll
        for(int t=0;t<4;t++){
          float pt = Psm[(w + 8*t)*Ll + m];
          FFMA2(acc[t], dup_f32(pt), bv);
        }
      }
      #pragma unroll
      for(int t=0;t<4;t++){
        int pr = w + 8*t;
        int l = half*128 + c*32 + pr;
        float2 o = unpack2(acc[t]);
        *(float2*)&cat[((size_t)(b*Ll + l))*MEMD + h*DKk + lane*2] = o;
      }
    }
    __syncthreads();
  }
}

// ---------------- res = h + cat; LayerNorm -> h (in place) ----------------
__global__ __launch_bounds__(256) void add_ln_kernel(
    float* __restrict__ hbuf, const float* __restrict__ cat,
    const float* __restrict__ g, const float* __restrict__ bln)
{
  __shared__ float rbuf[MEMD];
  __shared__ float red[8];
  int row = blockIdx.x, tid = threadIdx.x;
  float s = 0.f;
  for(int d=tid; d<MEMD; d+=256){
    float r = hbuf[(size_t)row*MEMD + d] + cat[(size_t)row*MEMD + d];
    rbuf[d] = r; s += r;
  }
  s = blockSum256(s, red);
  float mu = s * (1.f/MEMD);
  float v = 0.f;
  for(int d=tid; d<MEMD; d+=256){ float r = rbuf[d] - mu; v = fmaf(r, r, v); }
  v = blockSum256(v, red);
  float inv = 1.0f / sqrtf(v*(1.f/MEMD) + 1e-5f);
  for(int d=tid; d<MEMD; d+=256)
    hbuf[(size_t)row*MEMD + d] = (rbuf[d] - mu) * inv * g[d] + bln[d];
}

// ---------------- pooled = mean_l h; out = pooled @ Wc + bc ----------------
__global__ __launch_bounds__(256) void pool_classify_kernel(
    const float* __restrict__ hbuf, const float* __restrict__ Wc,
    const float* __restrict__ bc, float* __restrict__ out)
{
  __shared__ float pooled[MEMD];
  __shared__ float red[8];
  int b = blockIdx.x, tid = threadIdx.x;
  for(int d=tid; d<MEMD; d+=256){
    float s = 0.f;
    for(int l=0; l<Ll; l++) s += hbuf[((size_t)(b*Ll + l))*MEMD + d];
    pooled[d] = s * (1.f/Ll);
  }
  __syncthreads();
  for(int c=0; c<NCc; c++){
    float p = 0.f;
    for(int d=tid; d<MEMD; d+=256) p = fmaf(pooled[d], Wc[d*NCc + c], p);
    p = blockSum256(p, red);
    if(tid == 0) out[b*NCc + c] = p + bc[c];
  }
}

// ---------------- launcher ----------------
extern "C" void kernel_launch(void* const* d_in, const int* in_sizes, int n_in,
                              void* d_out, int out_size)
{
  const float* x    = (const float*)d_in[0];
  const float* wq   = (const float*)d_in[1];
  const float* bq   = (const float*)d_in[2];
  const float* wk   = (const float*)d_in[3];
  const float* bk   = (const float*)d_in[4];
  const float* w_in = (const float*)d_in[5];
  const float* b_in = (const float*)d_in[6];
  const float* Wh   = (const float*)d_in[7];
  const float* bh   = (const float*)d_in[8];
  const float* aw   = (const float*)d_in[9];
  const float* ab   = (const float*)d_in[10];
  const float* g_ln = (const float*)d_in[11];
  const float* b_ln = (const float*)d_in[12];
  const float* Wc   = (const float*)d_in[13];
  const float* bc   = (const float*)d_in[14];
  float* out = (float*)d_out;

  float *pq, *pk, *pscores, *ppattn, *pkth, *ph, *pproj, *pcat, *psi, *psj, *pwcat;
  unsigned char* padj;
  cudaGetSymbolAddress((void**)&pq, g_q);
  cudaGetSymbolAddress((void**)&pk, g_k);
  cudaGetSymbolAddress((void**)&pscores, g_scores);
  cudaGetSymbolAddress((void**)&ppattn, g_pattn);
  cudaGetSymbolAddress((void**)&pkth, g_kth);
  cudaGetSymbolAddress((void**)&padj, g_adj);
  cudaGetSymbolAddress((void**)&ph, g_h);
  cudaGetSymbolAddress((void**)&pproj, g_proj);
  cudaGetSymbolAddress((void**)&pcat, g_cat);
  cudaGetSymbolAddress((void**)&psi, g_si);
  cudaGetSymbolAddress((void**)&psj, g_sj);
  cudaGetSymbolAddress((void**)&pwcat, g_wcat);

  const int ATTN_SMEM = (Ll*DKk + 32*Ll + Ll + 128) * 4; // 85504 bytes
  cudaFuncSetAttribute(gat_attn_kernel, cudaFuncAttributeMaxDynamicSharedMemorySize, ATTN_SMEM);
  cudaFuncSetAttribute(gemm_tf32x3, cudaFuncAttributeMaxDynamicSharedMemorySize, TGEMM_SMEM);
  cudaFuncSetAttribute(qk_scores_tf32, cudaFuncAttributeMaxDynamicSharedMemorySize, TGEMM_SMEM);

  // q, k projections (3xTF32 tensor core)
  gemm_tf32x3<<<dim3(DIN/128, BL/128), 256, TGEMM_SMEM>>>(x, wq, bq, pq, BL, DIN, DIN);
  gemm_tf32x3<<<dim3(DIN/128, BL/128), 256, TGEMM_SMEM>>>(x, wk, bk, pk, BL, DIN, DIN);

  // scores + softmax + head-mean
  qk_scores_tf32<<<dim3(2, 2, Bb*Hh), 256, TGEMM_SMEM>>>(pq, pk, pscores);
  softmax_mean_kernel<<<Bb*Ll, 256>>>(pscores, ppattn);

  // top-k threshold + adjacency
  topk_select_kernel<<<Bb, 1024>>>(ppattn, pkth);
  build_adj_kernel<<<Bb*Ll, 256>>>(ppattn, pkth, padj);

  // h = x @ w_in + b_in (3xTF32)
  gemm_tf32x3<<<dim3((MEMD+127)/128, BL/128), 256, TGEMM_SMEM>>>(x, w_in, b_in, ph, BL, MEMD, DIN);

  // repack Wh into (layer, MEM, H*DK)
  repack_wh_kernel<<<(NLAYERS*Hh*MEMD*DKk + 255)/256, 256>>>(Wh, pwcat);

  for(int layer=0; layer<NLAYERS; layer++){
    gemm_tf32x3<<<dim3((MEMD+127)/128, BL/128), 256, TGEMM_SMEM>>>(
        ph, pwcat + (size_t)layer*MEMD*MEMD, bh + layer*MEMD, pproj, BL, MEMD, MEMD);
    sisj_kernel<<<(Bb*Hh*Ll + 127)/128, 128>>>(pproj, aw + layer*2*DKk, psi, psj);
    gat_attn_kernel<<<Bb*Hh*2, 256, ATTN_SMEM>>>(pproj, psi, psj, padj, ab + layer, pcat);
    add_ln_kernel<<<Bb*Ll, 256>>>(ph, pcat, g_ln + layer*MEMD, b_ln + layer*MEMD);
  }

  pool_classify_kernel<<<Bb, 256>>>(ph, Wc, bc, out);
}

// round 7
// speedup vs baseline: 1.3859x; 1.3859x over previous
#include <cuda_runtime.h>
#include <math.h>

#define Bb 64
#define Ll 256
#define DIN 768
#define MEMD 300
#define Hh 6
#define TOPK 1024
#define NCc 3
#define NLAYERS 2
#define DKk 50
#define BL (Bb*Ll)   // 16384

// ---------------- scratch (device globals; no runtime allocation) ----------------
__device__ float g_q[BL*DIN];
__device__ float g_k[BL*DIN];
__device__ float g_scores[Bb*Hh*Ll*Ll];
__device__ float g_pattn[Bb*Ll*Ll];
__device__ float g_kth[Bb];
__device__ unsigned char g_adj[Bb*Ll*Ll];
__device__ float g_h[BL*MEMD];
__device__ float g_proj[BL*MEMD];
__device__ float g_cat[BL*MEMD];
__device__ float g_si[Bb*Hh*Ll];
__device__ float g_sj[Bb*Hh*Ll];
__device__ float g_wcat[NLAYERS*MEMD*MEMD];
__device__ float g_poolpart[Bb*8*MEMD];

// ---------------- packed fp32x2 FMA helpers ----------------
#define FFMA2(acc, a2, b2) \
  asm("fma.rn.f32x2 %0, %1, %2, %3;" : "=l"(acc) : "l"(a2), "l"(b2), "l"(acc))

__device__ __forceinline__ unsigned long long dup_f32(float x){
  unsigned long long r;
  asm("mov.b64 %0, {%1, %1};" : "=l"(r) : "f"(x));
  return r;
}
__device__ __forceinline__ float2 unpack2(unsigned long long v){
  float2 c;
  asm("mov.b64 {%0, %1}, %2;" : "=f"(c.x), "=f"(c.y) : "l"(v));
  return c;
}

// ---------------- tf32 helpers ----------------
__device__ __forceinline__ unsigned f2tf32(float x){
  unsigned r; asm("cvt.rna.tf32.f32 %0, %1;" : "=r"(r) : "f"(x)); return r;
}
__device__ __forceinline__ void cvt_hilo(float v, float& h, float& l){
  unsigned hu = f2tf32(v);
  float hf = __uint_as_float(hu);
  h = hf;
  l = __uint_as_float(f2tf32(v - hf));
}
__device__ __forceinline__ void mma_tf32(float* d, const unsigned* a, const unsigned* b){
  asm("mma.sync.aligned.m16n8k8.row.col.f32.tf32.tf32.f32 "
      "{%0,%1,%2,%3},{%4,%5,%6,%7},{%8,%9},{%0,%1,%2,%3};"
      : "+f"(d[0]), "+f"(d[1]), "+f"(d[2]), "+f"(d[3])
      : "r"(a[0]), "r"(a[1]), "r"(a[2]), "r"(a[3]), "r"(b[0]), "r"(b[1]));
}

// ---------------- reduction helpers ----------------
__device__ __forceinline__ float warpSum(float v){
  #pragma unroll
  for(int o=16;o;o>>=1) v += __shfl_xor_sync(0xffffffffu, v, o);
  return v;
}
__device__ __forceinline__ float blockSum256(float v, float* sh){
  v = warpSum(v);
  int w = threadIdx.x >> 5;
  if((threadIdx.x & 31) == 0) sh[w] = v;
  __syncthreads();
  if(threadIdx.x < 8){
    float x = sh[threadIdx.x];
    #pragma unroll
    for(int o=4;o;o>>=1) x += __shfl_xor_sync(0xffu, x, o);
    if(threadIdx.x==0) sh[0] = x;
  }
  __syncthreads();
  float r = sh[0];
  __syncthreads();
  return r;
}

// =====================================================================
// 3xTF32 tensor-core GEMM (ROUND-5 layout, conflict-free scalar frags)
// C[M,N] = A[M,K] @ W[K,N] + bias. Block 128x128, BK=16, 8 warps (4x2).
// =====================================================================
#define GEMM_ASZ 2560   // 128*20
#define GEMM_WSZ 2176   // 16*136
#define GEMM_SMEM ((2*GEMM_ASZ*2 + 2*GEMM_WSZ*2)*4)  // 75776

__global__ __launch_bounds__(256) void gemm_tf32x3(
    const float* __restrict__ A, const float* __restrict__ W,
    const float* __restrict__ bias, float* __restrict__ C,
    int M, int N, int K)
{
  extern __shared__ float smdyn[];
  float* Ahi = smdyn;                 // [2][GEMM_ASZ]
  float* Alo = Ahi + 2*GEMM_ASZ;
  float* Whi = Alo + 2*GEMM_ASZ;      // [2][GEMM_WSZ]
  float* Wlo = Whi + 2*GEMM_WSZ;

  int tid = threadIdx.x, lane = tid & 31, wid = tid >> 5;
  int wm = wid & 3, wn = wid >> 2;
  int row0 = blockIdx.y*128, col0 = blockIdx.x*128;
  int nStages = (K + 15) >> 4;

  float acc[2][8][4];
  #pragma unroll
  for(int i=0;i<2;i++)
    #pragma unroll
    for(int j=0;j<8;j++)
      #pragma unroll
      for(int t=0;t<4;t++) acc[i][j][t] = 0.f;

  float4 pa[2], pw[2];

  #define GLOAD(k0)                                                         \
    {                                                                       \
      _Pragma("unroll")                                                     \
      for(int i=0;i<2;i++){                                                 \
        int f = tid + i*256; int m = f>>2, q = f&3;                         \
        int gk = (k0) + q*4;                                                \
        pa[i] = (gk < K) ? *(const float4*)&A[(size_t)(row0+m)*K + gk]      \
                         : make_float4(0.f,0.f,0.f,0.f);                    \
      }                                                                     \
      _Pragma("unroll")                                                     \
      for(int i=0;i<2;i++){                                                 \
        int f = tid + i*256; int kk = f>>5, n4 = f&31;                      \
        int gk = (k0) + kk, gc = col0 + n4*4;                               \
        pw[i] = (gk < K && gc < N) ? *(const float4*)&W[(size_t)gk*N + gc]  \
                                   : make_float4(0.f,0.f,0.f,0.f);          \
      }                                                                     \
    }

  #define SSTORE(p)                                                         \
    {                                                                       \
      _Pragma("unroll")                                                     \
      for(int i=0;i<2;i++){                                                 \
        int f = tid + i*256; int m = f>>2, q = f&3;                         \
        float4 v = pa[i]; float4 h, l;                                      \
        cvt_hilo(v.x, h.x, l.x); cvt_hilo(v.y, h.y, l.y);                   \
        cvt_hilo(v.z, h.z, l.z); cvt_hilo(v.w, h.w, l.w);                   \
        *(float4*)&Ahi[(p)*GEMM_ASZ + m*20 + q*4] = h;                      \
        *(float4*)&Alo[(p)*GEMM_ASZ + m*20 + q*4] = l;                      \
      }                                                                     \
      _Pragma("unroll")                                                     \
      for(int i=0;i<2;i++){                                                 \
        int f = tid + i*256; int kk = f>>5, n4 = f&31;                      \
        float4 v = pw[i]; float4 h, l;                                      \
        cvt_hilo(v.x, h.x, l.x); cvt_hilo(v.y, h.y, l.y);                   \
        cvt_hilo(v.z, h.z, l.z); cvt_hilo(v.w, h.w, l.w);                   \
        *(float4*)&Whi[(p)*GEMM_WSZ + kk*136 + n4*4] = h;                   \
        *(float4*)&Wlo[(p)*GEMM_WSZ + kk*136 + n4*4] = l;                   \
      }                                                                     \
    }

  GLOAD(0);
  SSTORE(0);
  __syncthreads();

  for(int s=0; s<nStages; s++){
    int p = s & 1;
    if(s+1 < nStages) GLOAD((s+1)*16);

    const float* Ah = Ahi + p*GEMM_ASZ;
    const float* Al = Alo + p*GEMM_ASZ;
    const float* Wh = Whi + p*GEMM_WSZ;
    const float* Wl = Wlo + p*GEMM_WSZ;

    #pragma unroll
    for(int k8=0; k8<16; k8+=8){
      int kA = k8 + (lane & 3);
      int mb = wm*32 + (lane >> 2);
      unsigned ah[2][4], al[2][4];
      #pragma unroll
      for(int mt=0; mt<2; mt++){
        int m0 = (mb + mt*16)*20;
        ah[mt][0] = __float_as_uint(Ah[m0 + kA]);
        ah[mt][1] = __float_as_uint(Ah[m0 + 160 + kA]);
        ah[mt][2] = __float_as_uint(Ah[m0 + kA + 4]);
        ah[mt][3] = __float_as_uint(Ah[m0 + 160 + kA + 4]);
        al[mt][0] = __float_as_uint(Al[m0 + kA]);
        al[mt][1] = __float_as_uint(Al[m0 + 160 + kA]);
        al[mt][2] = __float_as_uint(Al[m0 + kA + 4]);
        al[mt][3] = __float_as_uint(Al[m0 + 160 + kA + 4]);
      }
      int nb = wn*64 + (lane >> 2);
      int kB = (k8 + (lane & 3))*136;
      unsigned bh[8][2], bl[8][2];
      #pragma unroll
      for(int nt=0; nt<8; nt++){
        bh[nt][0] = __float_as_uint(Wh[kB + nb + nt*8]);
        bh[nt][1] = __float_as_uint(Wh[kB + 4*136 + nb + nt*8]);
        bl[nt][0] = __float_as_uint(Wl[kB + nb + nt*8]);
        bl[nt][1] = __float_as_uint(Wl[kB + 4*136 + nb + nt*8]);
      }
      #pragma unroll
      for(int mt=0; mt<2; mt++)
        #pragma unroll
        for(int nt=0; nt<8; nt++){
          mma_tf32(acc[mt][nt], ah[mt], bh[nt]);
          mma_tf32(acc[mt][nt], ah[mt], bl[nt]);
          mma_tf32(acc[mt][nt], al[mt], bh[nt]);
        }
    }

    if(s+1 < nStages){
      SSTORE((s+1)&1);
      __syncthreads();
    }
  }

  #pragma unroll
  for(int mt=0; mt<2; mt++){
    int r0 = row0 + wm*32 + mt*16 + (lane >> 2);
    #pragma unroll
    for(int nt=0; nt<8; nt++){
      int c = col0 + wn*64 + nt*8 + (lane & 3)*2;
      if(c < N){
        float2 bs = *(const float2*)&bias[c];
        float2 o0; o0.x = acc[mt][nt][0] + bs.x; o0.y = acc[mt][nt][1] + bs.y;
        *(float2*)&C[(size_t)r0*N + c] = o0;
        float2 o1; o1.x = acc[mt][nt][2] + bs.x; o1.y = acc[mt][nt][3] + bs.y;
        *(float2*)&C[(size_t)(r0+8)*N + c] = o1;
      }
    }
  }
  #undef GLOAD
  #undef SSTORE
}

// =====================================================================
// QK^T scores, 3xTF32, NT. Both operands m-major stride-20 (round-5
// proven conflict-free fragment pattern). K=128. Fused 1/sqrt(128).
// =====================================================================
#define QK_ASZ 2560                 // 128*20
#define QK_SMEM (4*2*QK_ASZ*4)      // 81920

__global__ __launch_bounds__(256) void qk_scores_tf32(
    const float* __restrict__ q, const float* __restrict__ k,
    float* __restrict__ scores)
{
  extern __shared__ float smq[];
  float* Qhi = smq;                  // [2][QK_ASZ]
  float* Qlo = Qhi + 2*QK_ASZ;
  float* Khi = Qlo + 2*QK_ASZ;
  float* Klo = Khi + 2*QK_ASZ;

  int bh = blockIdx.z;
  int b = bh / Hh, h = bh - b*Hh;
  const float* Ag = q + (size_t)b*Ll*DIN + (size_t)h*128;
  const float* Bg = k + (size_t)b*Ll*DIN + (size_t)h*128;

  int tid = threadIdx.x, lane = tid & 31, wid = tid >> 5;
  int wm = wid & 3, wn = wid >> 2;
  int row0 = blockIdx.y*128, col0 = blockIdx.x*128;
  const int nStages = 8;  // K=128

  float acc[2][8][4];
  #pragma unroll
  for(int i=0;i<2;i++)
    #pragma unroll
    for(int j=0;j<8;j++)
      #pragma unroll
      for(int t=0;t<4;t++) acc[i][j][t] = 0.f;

  float4 pa[2], pb[2];

  #define QGLOAD(k0)                                                        \
    {                                                                       \
      _Pragma("unroll")                                                     \
      for(int i=0;i<2;i++){                                                 \
        int f = tid + i*256; int m = f>>2, kq = f&3;                        \
        pa[i] = *(const float4*)&Ag[(size_t)(row0+m)*DIN + (k0) + kq*4];    \
        pb[i] = *(const float4*)&Bg[(size_t)(col0+m)*DIN + (k0) + kq*4];    \
      }                                                                     \
    }

  #define QSSTORE(p)                                                        \
    {                                                                       \
      _Pragma("unroll")                                                     \
      for(int i=0;i<2;i++){                                                 \
        int f = tid + i*256; int m = f>>2, kq = f&3;                        \
        float4 h, l;                                                        \
        cvt_hilo(pa[i].x, h.x, l.x); cvt_hilo(pa[i].y, h.y, l.y);           \
        cvt_hilo(pa[i].z, h.z, l.z); cvt_hilo(pa[i].w, h.w, l.w);           \
        *(float4*)&Qhi[(p)*QK_ASZ + m*20 + kq*4] = h;                       \
        *(float4*)&Qlo[(p)*QK_ASZ + m*20 + kq*4] = l;                       \
        cvt_hilo(pb[i].x, h.x, l.x); cvt_hilo(pb[i].y, h.y, l.y);           \
        cvt_hilo(pb[i].z, h.z, l.z); cvt_hilo(pb[i].w, h.w, l.w);           \
        *(float4*)&Khi[(p)*QK_ASZ + m*20 + kq*4] = h;                       \
        *(float4*)&Klo[(p)*QK_ASZ + m*20 + kq*4] = l;                       \
      }                                                                     \
    }

  QGLOAD(0);
  QSSTORE(0);
  __syncthreads();

  for(int s=0; s<nStages; s++){
    int p = s & 1;
    if(s+1 < nStages) QGLOAD((s+1)*16);

    const float* Ah = Qhi + p*QK_ASZ;
    const float* Al = Qlo + p*QK_ASZ;
    const float* Bh = Khi + p*QK_ASZ;
    const float* Blp = Klo + p*QK_ASZ;

    #pragma unroll
    for(int k8=0; k8<16; k8+=8){
      int kA = k8 + (lane & 3);
      int mb = wm*32 + (lane >> 2);
      unsigned ah[2][4], al[2][4];
      #pragma unroll
      for(int mt=0; mt<2; mt++){
        int m0 = (mb + mt*16)*20;
        ah[mt][0] = __float_as_uint(Ah[m0 + kA]);
        ah[mt][1] = __float_as_uint(Ah[m0 + 160 + kA]);
        ah[mt][2] = __float_as_uint(Ah[m0 + kA + 4]);
        ah[mt][3] = __float_as_uint(Ah[m0 + 160 + kA + 4]);
        al[mt][0] = __float_as_uint(Al[m0 + kA]);
        al[mt][1] = __float_as_uint(Al[m0 + 160 + kA]);
        al[mt][2] = __float_as_uint(Al[m0 + kA + 4]);
        al[mt][3] = __float_as_uint(Al[m0 + 160 + kA + 4]);
      }
      int nbase = wn*64 + (lane >> 2);
      unsigned bhf[8][2], blf[8][2];
      #pragma unroll
      for(int nt=0; nt<8; nt++){
        int n0 = (nbase + nt*8)*20;
        bhf[nt][0] = __float_as_uint(Bh[n0 + kA]);
        bhf[nt][1] = __float_as_uint(Bh[n0 + kA + 4]);
        blf[nt][0] = __float_as_uint(Blp[n0 + kA]);
        blf[nt][1] = __float_as_uint(Blp[n0 + kA + 4]);
      }
      #pragma unroll
      for(int mt=0; mt<2; mt++)
        #pragma unroll
        for(int nt=0; nt<8; nt++){
          mma_tf32(acc[mt][nt], ah[mt], bhf[nt]);
          mma_tf32(acc[mt][nt], ah[mt], blf[nt]);
          mma_tf32(acc[mt][nt], al[mt], bhf[nt]);
        }
    }

    if(s+1 < nStages){
      QSSTORE((s+1)&1);
      __syncthreads();
    }
  }

  const float scale = 0.08838834764831845f; // 1/sqrt(128)
  #pragma unroll
  for(int mt=0; mt<2; mt++){
    int r0 = row0 + wm*32 + mt*16 + (lane >> 2);
    #pragma unroll
    for(int nt=0; nt<8; nt++){
      int c = col0 + wn*64 + nt*8 + (lane & 3)*2;
      float2 o0; o0.x = acc[mt][nt][0]*scale; o0.y = acc[mt][nt][1]*scale;
      *(float2*)&scores[((size_t)bh*Ll + r0)*Ll + c] = o0;
      float2 o1; o1.x = acc[mt][nt][2]*scale; o1.y = acc[mt][nt][3]*scale;
      *(float2*)&scores[((size_t)bh*Ll + r0 + 8)*Ll + c] = o1;
    }
  }
  #undef QGLOAD
  #undef QSSTORE
}

// ---------------- softmax over m per (b,l), all 6 heads batched ----------------
__global__ __launch_bounds__(256) void softmax_mean_kernel(
    const float* __restrict__ scores, float* __restrict__ pattn)
{
  __shared__ float red1[Hh][8];
  __shared__ float r1[Hh];
  __shared__ float red2[Hh][8];
  __shared__ float r2[Hh];
  int bl = blockIdx.x;
  int b = bl >> 8, l = bl & 255;
  int m = threadIdx.x, w = m >> 5, lane = m & 31;
  const float* base = scores + ((size_t)(b*Hh)*Ll + l)*Ll + m;
  float s[Hh];
  #pragma unroll
  for(int h=0;h<Hh;h++) s[h] = base[(size_t)h*Ll*Ll];

  float v[Hh];
  #pragma unroll
  for(int h=0;h<Hh;h++){
    v[h] = s[h];
    #pragma unroll
    for(int o=16;o;o>>=1) v[h] = fmaxf(v[h], __shfl_xor_sync(0xffffffffu, v[h], o));
  }
  if(lane == 0){
    #pragma unroll
    for(int h=0;h<Hh;h++) red1[h][w] = v[h];
  }
  __syncthreads();
  if(m < Hh){
    float x = red1[m][0];
    #pragma unroll
    for(int j=1;j<8;j++) x = fmaxf(x, red1[m][j]);
    r1[m] = x;
  }
  __syncthreads();

  float e[Hh];
  #pragma unroll
  for(int h=0;h<Hh;h++){
    e[h] = expf(s[h] - r1[h]);
    v[h] = e[h];
    #pragma unroll
    for(int o=16;o;o>>=1) v[h] += __shfl_xor_sync(0xffffffffu, v[h], o);
  }
  if(lane == 0){
    #pragma unroll
    for(int h=0;h<Hh;h++) red2[h][w] = v[h];
  }
  __syncthreads();
  if(m < Hh){
    float x = red2[m][0];
    #pragma unroll
    for(int j=1;j<8;j++) x += red2[m][j];
    r2[m] = x;
  }
  __syncthreads();

  float acc = 0.f;
  #pragma unroll
  for(int h=0;h<Hh;h++) acc += e[h] / r2[h];
  pattn[(size_t)bl*Ll + m] = acc * (1.f/6.f);
}

// ---------------- exact 1024th-largest per batch via radix select ----------------
__global__ __launch_bounds__(1024) void topk_select_kernel(
    const float* __restrict__ pattn, float* __restrict__ kth)
{
  int b = blockIdx.x;
  int tid = threadIdx.x;
  const unsigned* v = (const unsigned*)(pattn + (size_t)b*Ll*Ll);
  __shared__ unsigned hist[256];
  __shared__ unsigned s_prefix;
  __shared__ int s_k;
  if(tid == 0){ s_prefix = 0u; s_k = TOPK; }
  __syncthreads();
  for(int pass=3; pass>=0; --pass){
    int shift = pass*8;
    if(tid < 256) hist[tid] = 0u;
    __syncthreads();
    unsigned prefix = s_prefix;
    unsigned mask = (pass==3) ? 0u : (0xFFFFFFFFu << ((pass+1)*8));
    for(int i=tid; i<Ll*Ll; i+=1024){
      unsigned x = v[i];
      if((x & mask) == prefix) atomicAdd(&hist[(x >> shift) & 0xFF], 1u);
    }
    __syncthreads();
    if(tid == 0){
      int k = s_k, cum = 0;
      unsigned byte = 0;
      for(int bb=255; bb>=0; --bb){
        int c = (int)hist[bb];
        if(cum + c >= k){ byte = (unsigned)bb; s_k = k - cum; break; }
        cum += c;
      }
      s_prefix = prefix | (byte << shift);
    }
    __syncthreads();
  }
  if(tid == 0) kth[b] = __uint_as_float(s_prefix);
}

// ---------------- adjacency mask (tiled, coalesced transpose) ----------------
// block = (i-tile of 32 rows, batch). Loads row tile + padded column tile
// through smem; all global accesses coalesced.
__global__ __launch_bounds__(256) void build_adj_tiled(
    const float* __restrict__ pattn, const float* __restrict__ kth,
    unsigned char* __restrict__ adj)
{
  extern __shared__ float smadj[];
  float* Pi = smadj;          // [32][256]
  float* Tj = Pi + 32*256;    // [256][33]

  int b = blockIdx.y, it = blockIdx.x;
  int i0 = it*32;
  int tid = threadIdx.x, w = tid >> 5, lane = tid & 31;
  const float* p = pattn + (size_t)b*Ll*Ll;

  // row tile: rows i0..i0+31, all 256 cols (coalesced)
  #pragma unroll
  for(int rr=0; rr<4; rr++){
    int r = w*4 + rr;
    #pragma unroll
    for(int cc=0; cc<8; cc++){
      int c = lane + cc*32;
      Pi[r*256 + c] = p[(size_t)(i0+r)*Ll + c];
    }
  }
  // column tile: all 256 rows, cols i0..i0+31 (each warp-row read = 128B contiguous)
  #pragma unroll
  for(int jj=0; jj<32; jj++){
    int j = w*32 + jj;
    Tj[j*33 + lane] = p[(size_t)j*Ll + i0 + lane];
  }
  __syncthreads();

  float t = kth[b];
  unsigned char* arow = adj + (size_t)b*Ll*Ll;
  #pragma unroll 4
  for(int ii=0; ii<32; ii++){
    int i = i0 + ii, j = tid;
    bool e = (i==j) || (Pi[ii*256 + j] >= t) || (Tj[j*33 + ii] >= t);
    arow[(size_t)i*Ll + j] = e ? 1 : 0;
  }
}
#define ADJ_SMEM ((32*256 + 256*33)*4)  // 66560

// ---------------- repack Wh(layer,h,d,k) -> Wcat(layer, d, h*50+k) ----------------
__global__ void repack_wh_kernel(const float* __restrict__ Wh, float* __restrict__ wcat){
  int idx = blockIdx.x*blockDim.x + threadIdx.x;
  if(idx >= NLAYERS*Hh*MEMD*DKk) return;
  int layer = idx / (Hh*MEMD*DKk);
  int r = idx - layer*(Hh*MEMD*DKk);
  int h = r / (MEMD*DKk);
  int r2 = r - h*(MEMD*DKk);
  int d = r2 / DKk;
  int kk = r2 - d*DKk;
  wcat[(size_t)layer*MEMD*MEMD + (size_t)d*MEMD + h*DKk + kk] = Wh[idx];
}

// ---------------- s_i, s_j per (b,h,l) ----------------
__global__ void sisj_kernel(const float* __restrict__ proj, const float* __restrict__ awl,
                            float* __restrict__ si, float* __restrict__ sj)
{
  int idx = blockIdx.x*blockDim.x + threadIdx.x;
  if(idx >= Bb*Hh*Ll) return;
  int b = idx / (Hh*Ll);
  int r = idx - b*(Hh*Ll);
  int h = r / Ll;
  int l = r - h*Ll;
  const float* pr = proj + (((size_t)(b*Ll + l))*Hh + h)*DKk;
  const float* w1 = awl;
  const float* w2 = awl + DKk;
  float a = 0.f, c = 0.f;
  #pragma unroll
  for(int k2=0;k2<DKk;k2++){ float pv = pr[k2]; a = fmaf(pv, w1[k2], a); c = fmaf(pv, w2[k2], c); }
  si[idx] = a; sj[idx] = c;
}

// =====================================================================
// fused GAT attention: block per (b,h,half). Two-phase chunked.
// =====================================================================
__global__ __launch_bounds__(256) void gat_attn_kernel(
    const float* __restrict__ proj, const float* __restrict__ si, const float* __restrict__ sj,
    const unsigned char* __restrict__ adj, const float* __restrict__ abp,
    float* __restrict__ cat)
{
  extern __shared__ float smx[];
  float* projS = smx;
  float* Psm   = projS + Ll*DKk;
  float* sjS   = Psm + 32*Ll;
  float* siS   = sjS + Ll;

  int bhh = blockIdx.x;
  int bh = bhh >> 1, half = bhh & 1;
  int b = bh / Hh, h = bh - b*Hh;
  int tid = threadIdx.x;
  int lane = tid & 31, w = tid >> 5;

  {
    const float* projBase = proj + ((size_t)(b*Ll))*MEMD + h*DKk;
    float2* dst = (float2*)projS;
    for(int e=tid; e<Ll*25; e+=256){
      int m = e / 25, t = e - m*25;
      dst[m*25+t] = ((const float2*)(projBase + (size_t)m*MEMD))[t];
    }
  }
  sjS[tid] = sj[(size_t)bh*Ll + tid];
  if(tid < 128) siS[tid] = si[(size_t)bh*Ll + half*128 + tid];
  __syncthreads();

  float abv = abp[0];
  const unsigned char* adjb = adj + (size_t)b*Ll*Ll;

  for(int c=0; c<4; c++){
    #pragma unroll
    for(int rr=0; rr<4; rr++){
      int pr = w*4 + rr;
      int l = half*128 + c*32 + pr;
      float si_l = siS[c*32 + pr];
      const unsigned char* arow = adjb + (size_t)l*Ll;
      float pv[8]; bool okv[8];
      float mx = -3.0e38f;
      #pragma unroll
      for(int j=0;j<8;j++){
        int m = lane + j*32;
        float sval = si_l + sjS[m] + abv;
        sval = (sval > 0.f) ? sval : 0.2f*sval;
        bool ok = arow[m] != 0;
        okv[j] = ok; pv[j] = sval;
        mx = fmaxf(mx, ok ? sval : -3.0e38f);
      }
      #pragma unroll
      for(int o=16;o;o>>=1) mx = fmaxf(mx, __shfl_xor_sync(0xffffffffu, mx, o));
      float ev[8];
      float s = 0.f;
      #pragma unroll
      for(int j=0;j<8;j++){
        ev[j] = okv[j] ? expf(pv[j] - mx) : 0.f;
        s += ev[j];
      }
      #pragma unroll
      for(int o=16;o;o>>=1) s += __shfl_xor_sync(0xffffffffu, s, o);
      float inv = 1.0f / s;
      #pragma unroll
      for(int j=0;j<8;j++)
        Psm[pr*Ll + lane + j*32] = ev[j] * inv;
    }
    __syncthreads();

    if(lane < 25){
      unsigned long long acc[4] = {0ull,0ull,0ull,0ull};
      const unsigned long long* Vp = (const unsigned long long*)projS;
      #pragma unroll 4
      for(int m=0; m<Ll; m++){
        unsigned long long bv = Vp[m*25 + lane];
        #pragma unroll
        for(int t=0;t<4;t++){
          float pt = Psm[(w + 8*t)*Ll + m];
          FFMA2(acc[t], dup_f32(pt), bv);
        }
      }
      #pragma unroll
      for(int t=0;t<4;t++){
        int pr = w + 8*t;
        int l = half*128 + c*32 + pr;
        float2 o = unpack2(acc[t]);
        *(float2*)&cat[((size_t)(b*Ll + l))*MEMD + h*DKk + lane*2] = o;
      }
    }
    __syncthreads();
  }
}

// ---------------- res = h + cat; LayerNorm -> h (in place) ----------------
__global__ __launch_bounds__(256) void add_ln_kernel(
    float* __restrict__ hbuf, const float* __restrict__ cat,
    const float* __restrict__ g, const float* __restrict__ bln)
{
  __shared__ float rbuf[MEMD];
  __shared__ float red[8];
  int row = blockIdx.x, tid = threadIdx.x;
  float s = 0.f;
  for(int d=tid; d<MEMD; d+=256){
    float r = hbuf[(size_t)row*MEMD + d] + cat[(size_t)row*MEMD + d];
    rbuf[d] = r; s += r;
  }
  s = blockSum256(s, red);
  float mu = s * (1.f/MEMD);
  float v = 0.f;
  for(int d=tid; d<MEMD; d+=256){ float r = rbuf[d] - mu; v = fmaf(r, r, v); }
  v = blockSum256(v, red);
  float inv = 1.0f / sqrtf(v*(1.f/MEMD) + 1e-5f);
  for(int d=tid; d<MEMD; d+=256)
    hbuf[(size_t)row*MEMD + d] = (rbuf[d] - mu) * inv * g[d] + bln[d];
}

// ---------------- pool partials: grid (8 chunks, 64 b) ----------------
__global__ __launch_bounds__(256) void pool_part_kernel(
    const float* __restrict__ hbuf, float* __restrict__ part)
{
  int b = blockIdx.y, c = blockIdx.x;
  int tid = threadIdx.x;
  const float* base = hbuf + ((size_t)(b*Ll + c*32))*MEMD;
  for(int d=tid; d<MEMD; d+=256){
    float s = 0.f;
    #pragma unroll 4
    for(int l=0; l<32; l++) s += base[(size_t)l*MEMD + d];
    part[((size_t)(b*8 + c))*MEMD + d] = s;
  }
}

// ---------------- final: pooled = sum(parts)/L; out = pooled @ Wc + bc ----------------
__global__ __launch_bounds__(256) void pool_classify_kernel(
    const float* __restrict__ part, const float* __restrict__ Wc,
    const float* __restrict__ bc, float* __restrict__ out)
{
  __shared__ float pooled[MEMD];
  __shared__ float red[8];
  int b = blockIdx.x, tid = threadIdx.x;
  for(int d=tid; d<MEMD; d+=256){
    float s = 0.f;
    #pragma unroll
    for(int c=0; c<8; c++) s += part[((size_t)(b*8 + c))*MEMD + d];
    pooled[d] = s * (1.f/Ll);
  }
  __syncthreads();
  for(int c=0; c<NCc; c++){
    float p = 0.f;
    for(int d=tid; d<MEMD; d+=256) p = fmaf(pooled[d], Wc[d*NCc + c], p);
    p = blockSum256(p, red);
    if(tid == 0) out[b*NCc + c] = p + bc[c];
  }
}

// ---------------- launcher ----------------
extern "C" void kernel_launch(void* const* d_in, const int* in_sizes, int n_in,
                              void* d_out, int out_size)
{
  const float* x    = (const float*)d_in[0];
  const float* wq   = (const float*)d_in[1];
  const float* bq   = (const float*)d_in[2];
  const float* wk   = (const float*)d_in[3];
  const float* bk   = (const float*)d_in[4];
  const float* w_in = (const float*)d_in[5];
  const float* b_in = (const float*)d_in[6];
  const float* Wh   = (const float*)d_in[7];
  const float* bh   = (const float*)d_in[8];
  const float* aw   = (const float*)d_in[9];
  const float* ab   = (const float*)d_in[10];
  const float* g_ln = (const float*)d_in[11];
  const float* b_ln = (const float*)d_in[12];
  const float* Wc   = (const float*)d_in[13];
  const float* bc   = (const float*)d_in[14];
  float* out = (float*)d_out;

  float *pq, *pk, *pscores, *ppattn, *pkth, *ph, *pproj, *pcat, *psi, *psj, *pwcat, *ppool;
  unsigned char* padj;
  cudaGetSymbolAddress((void**)&pq, g_q);
  cudaGetSymbolAddress((void**)&pk, g_k);
  cudaGetSymbolAddress((void**)&pscores, g_scores);
  cudaGetSymbolAddress((void**)&ppattn, g_pattn);
  cudaGetSymbolAddress((void**)&pkth, g_kth);
  cudaGetSymbolAddress((void**)&padj, g_adj);
  cudaGetSymbolAddress((void**)&ph, g_h);
  cudaGetSymbolAddress((void**)&pproj, g_proj);
  cudaGetSymbolAddress((void**)&pcat, g_cat);
  cudaGetSymbolAddress((void**)&psi, g_si);
  cudaGetSymbolAddress((void**)&psj, g_sj);
  cudaGetSymbolAddress((void**)&pwcat, g_wcat);
  cudaGetSymbolAddress((void**)&ppool, g_poolpart);

  const int ATTN_SMEM = (Ll*DKk + 32*Ll + Ll + 128) * 4; // 85504 bytes
  cudaFuncSetAttribute(gat_attn_kernel, cudaFuncAttributeMaxDynamicSharedMemorySize, ATTN_SMEM);
  cudaFuncSetAttribute(gemm_tf32x3, cudaFuncAttributeMaxDynamicSharedMemorySize, GEMM_SMEM);
  cudaFuncSetAttribute(qk_scores_tf32, cudaFuncAttributeMaxDynamicSharedMemorySize, QK_SMEM);
  cudaFuncSetAttribute(build_adj_tiled, cudaFuncAttributeMaxDynamicSharedMemorySize, ADJ_SMEM);

  // q, k projections (3xTF32 tensor core)
  gemm_tf32x3<<<dim3(DIN/128, BL/128), 256, GEMM_SMEM>>>(x, wq, bq, pq, BL, DIN, DIN);
  gemm_tf32x3<<<dim3(DIN/128, BL/128), 256, GEMM_SMEM>>>(x, wk, bk, pk, BL, DIN, DIN);

  // scores (3xTF32) + softmax + head-mean
  qk_scores_tf32<<<dim3(2, 2, Bb*Hh), 256, QK_SMEM>>>(pq, pk, pscores);
  softmax_mean_kernel<<<Bb*Ll, 256>>>(pscores, ppattn);

  // top-k threshold + adjacency
  topk_select_kernel<<<Bb, 1024>>>(ppattn, pkth);
  build_adj_tiled<<<dim3(8, Bb), 256, ADJ_SMEM>>>(ppattn, pkth, padj);

  // h = x @ w_in + b_in (3xTF32)
  gemm_tf32x3<<<dim3((MEMD+127)/128, BL/128), 256, GEMM_SMEM>>>(x, w_in, b_in, ph, BL, MEMD, DIN);

  // repack Wh into (layer, MEM, H*DK)
  repack_wh_kernel<<<(NLAYERS*Hh*MEMD*DKk + 255)/256, 256>>>(Wh, pwcat);

  for(int layer=0; layer<NLAYERS; layer++){
    gemm_tf32x3<<<dim3((MEMD+127)/128, BL/128), 256, GEMM_SMEM>>>(
        ph, pwcat + (size_t)layer*MEMD*MEMD, bh + layer*MEMD, pproj, BL, MEMD, MEMD);
    sisj_kernel<<<(Bb*Hh*Ll + 127)/128, 128>>>(pproj, aw + layer*2*DKk, psi, psj);
    gat_attn_kernel<<<Bb*Hh*2, 256, ATTN_SMEM>>>(pproj, psi, psj, padj, ab + layer, pcat);
    add_ln_kernel<<<Bb*Ll, 256>>>(ph, pcat, g_ln + layer*MEMD, b_ln + layer*MEMD);
  }

  pool_part_kernel<<<dim3(8, Bb), 256>>>(ph, ppool);
  pool_classify_kernel<<<Bb, 256>>>(ppool, Wc, bc, out);
}

// round 8
// speedup vs baseline: 1.3899x; 1.0028x over previous
#include <cuda_runtime.h>
#include <math.h>

#define Bb 64
#define Ll 256
#define DIN 768
#define MEMD 300
#define Hh 6
#define TOPK 1024
#define NCc 3
#define NLAYERS 2
#define DKk 50
#define BL (Bb*Ll)   // 16384

// ---------------- scratch (device globals; no runtime allocation) ----------------
__device__ float g_q[BL*DIN];
__device__ float g_k[BL*DIN];
__device__ float g_scores[Bb*Hh*Ll*Ll];
__device__ float g_pattn[Bb*Ll*Ll];
__device__ float g_kth[Bb];
__device__ unsigned char g_adj[Bb*Ll*Ll];
__device__ float g_h[BL*MEMD];
__device__ float g_proj[BL*MEMD];
__device__ float g_cat[BL*MEMD];
__device__ float g_si[Bb*Hh*Ll];
__device__ float g_sj[Bb*Hh*Ll];
__device__ float g_wcat[NLAYERS*MEMD*MEMD];
__device__ float g_poolpart[Bb*8*MEMD];

// ---------------- packed fp32x2 FMA helpers ----------------
#define FFMA2(acc, a2, b2) \
  asm("fma.rn.f32x2 %0, %1, %2, %3;" : "=l"(acc) : "l"(a2), "l"(b2), "l"(acc))

__device__ __forceinline__ unsigned long long dup_f32(float x){
  unsigned long long r;
  asm("mov.b64 %0, {%1, %1};" : "=l"(r) : "f"(x));
  return r;
}
__device__ __forceinline__ float2 unpack2(unsigned long long v){
  float2 c;
  asm("mov.b64 {%0, %1}, %2;" : "=f"(c.x), "=f"(c.y) : "l"(v));
  return c;
}

// ---------------- tf32 helpers ----------------
__device__ __forceinline__ unsigned f2tf32(float x){
  unsigned r; asm("cvt.rna.tf32.f32 %0, %1;" : "=r"(r) : "f"(x)); return r;
}
__device__ __forceinline__ void cvt_hilo(float v, float& h, float& l){
  unsigned hu = f2tf32(v);
  float hf = __uint_as_float(hu);
  h = hf;
  l = __uint_as_float(f2tf32(v - hf));
}
__device__ __forceinline__ void mma_tf32(float* d, const unsigned* a, const unsigned* b){
  asm("mma.sync.aligned.m16n8k8.row.col.f32.tf32.tf32.f32 "
      "{%0,%1,%2,%3},{%4,%5,%6,%7},{%8,%9},{%0,%1,%2,%3};"
      : "+f"(d[0]), "+f"(d[1]), "+f"(d[2]), "+f"(d[3])
      : "r"(a[0]), "r"(a[1]), "r"(a[2]), "r"(a[3]), "r"(b[0]), "r"(b[1]));
}

// ---------------- reduction helpers ----------------
__device__ __forceinline__ float warpSum(float v){
  #pragma unroll
  for(int o=16;o;o>>=1) v += __shfl_xor_sync(0xffffffffu, v, o);
  return v;
}
__device__ __forceinline__ float blockSum256(float v, float* sh){
  v = warpSum(v);
  int w = threadIdx.x >> 5;
  if((threadIdx.x & 31) == 0) sh[w] = v;
  __syncthreads();
  if(threadIdx.x < 8){
    float x = sh[threadIdx.x];
    #pragma unroll
    for(int o=4;o;o>>=1) x += __shfl_xor_sync(0xffu, x, o);
    if(threadIdx.x==0) sh[0] = x;
  }
  __syncthreads();
  float r = sh[0];
  __syncthreads();
  return r;
}

// =====================================================================
// 3xTF32 tensor-core GEMM (ROUND-5 layout, conflict-free scalar frags)
// C[M,N] = A[M,K] @ W[K,N] + bias. Block 128x128, BK=16, 8 warps (4x2).
// =====================================================================
#define GEMM_ASZ 2560   // 128*20
#define GEMM_WSZ 2176   // 16*136
#define GEMM_SMEM ((2*GEMM_ASZ*2 + 2*GEMM_WSZ*2)*4)  // 75776

__global__ __launch_bounds__(256) void gemm_tf32x3(
    const float* __restrict__ A, const float* __restrict__ W,
    const float* __restrict__ bias, float* __restrict__ C,
    int M, int N, int K)
{
  extern __shared__ float smdyn[];
  float* Ahi = smdyn;                 // [2][GEMM_ASZ]
  float* Alo = Ahi + 2*GEMM_ASZ;
  float* Whi = Alo + 2*GEMM_ASZ;      // [2][GEMM_WSZ]
  float* Wlo = Whi + 2*GEMM_WSZ;

  int tid = threadIdx.x, lane = tid & 31, wid = tid >> 5;
  int wm = wid & 3, wn = wid >> 2;
  int row0 = blockIdx.y*128, col0 = blockIdx.x*128;
  int nStages = (K + 15) >> 4;

  float acc[2][8][4];
  #pragma unroll
  for(int i=0;i<2;i++)
    #pragma unroll
    for(int j=0;j<8;j++)
      #pragma unroll
      for(int t=0;t<4;t++) acc[i][j][t] = 0.f;

  float4 pa[2], pw[2];

  #define GLOAD(k0)                                                         \
    {                                                                       \
      _Pragma("unroll")                                                     \
      for(int i=0;i<2;i++){                                                 \
        int f = tid + i*256; int m = f>>2, q = f&3;                         \
        int gk = (k0) + q*4;                                                \
        pa[i] = (gk < K) ? *(const float4*)&A[(size_t)(row0+m)*K + gk]      \
                         : make_float4(0.f,0.f,0.f,0.f);                    \
      }                                                                     \
      _Pragma("unroll")                                                     \
      for(int i=0;i<2;i++){                                                 \
        int f = tid + i*256; int kk = f>>5, n4 = f&31;                      \
        int gk = (k0) + kk, gc = col0 + n4*4;                               \
        pw[i] = (gk < K && gc < N) ? *(const float4*)&W[(size_t)gk*N + gc]  \
                                   : make_float4(0.f,0.f,0.f,0.f);          \
      }                                                                     \
    }

  #define SSTORE(p)                                                         \
    {                                                                       \
      _Pragma("unroll")                                                     \
      for(int i=0;i<2;i++){                                                 \
        int f = tid + i*256; int m = f>>2, q = f&3;                         \
        float4 v = pa[i]; float4 h, l;                                      \
        cvt_hilo(v.x, h.x, l.x); cvt_hilo(v.y, h.y, l.y);                   \
        cvt_hilo(v.z, h.z, l.z); cvt_hilo(v.w, h.w, l.w);                   \
        *(float4*)&Ahi[(p)*GEMM_ASZ + m*20 + q*4] = h;                      \
        *(float4*)&Alo[(p)*GEMM_ASZ + m*20 + q*4] = l;                      \
      }                                                                     \
      _Pragma("unroll")                                                     \
      for(int i=0;i<2;i++){                                                 \
        int f = tid + i*256; int kk = f>>5, n4 = f&31;                      \
        float4 v = pw[i]; float4 h, l;                                      \
        cvt_hilo(v.x, h.x, l.x); cvt_hilo(v.y, h.y, l.y);                   \
        cvt_hilo(v.z, h.z, l.z); cvt_hilo(v.w, h.w, l.w);                   \
        *(float4*)&Whi[(p)*GEMM_WSZ + kk*136 + n4*4] = h;                   \
        *(float4*)&Wlo[(p)*GEMM_WSZ + kk*136 + n4*4] = l;                   \
      }                                                                     \
    }

  GLOAD(0);
  SSTORE(0);
  __syncthreads();

  for(int s=0; s<nStages; s++){
    int p = s & 1;
    if(s+1 < nStages) GLOAD((s+1)*16);

    const float* Ah = Ahi + p*GEMM_ASZ;
    const float* Al = Alo + p*GEMM_ASZ;
    const float* Wh = Whi + p*GEMM_WSZ;
    const float* Wl = Wlo + p*GEMM_WSZ;

    #pragma unroll
    for(int k8=0; k8<16; k8+=8){
      int kA = k8 + (lane & 3);
      int mb = wm*32 + (lane >> 2);
      unsigned ah[2][4], al[2][4];
      #pragma unroll
      for(int mt=0; mt<2; mt++){
        int m0 = (mb + mt*16)*20;
        ah[mt][0] = __float_as_uint(Ah[m0 + kA]);
        ah[mt][1] = __float_as_uint(Ah[m0 + 160 + kA]);
        ah[mt][2] = __float_as_uint(Ah[m0 + kA + 4]);
        ah[mt][3] = __float_as_uint(Ah[m0 + 160 + kA + 4]);
        al[mt][0] = __float_as_uint(Al[m0 + kA]);
        al[mt][1] = __float_as_uint(Al[m0 + 160 + kA]);
        al[mt][2] = __float_as_uint(Al[m0 + kA + 4]);
        al[mt][3] = __float_as_uint(Al[m0 + 160 + kA + 4]);
      }
      int nb = wn*64 + (lane >> 2);
      int kB = (k8 + (lane & 3))*136;
      unsigned bh[8][2], bl[8][2];
      #pragma unroll
      for(int nt=0; nt<8; nt++){
        bh[nt][0] = __float_as_uint(Wh[kB + nb + nt*8]);
        bh[nt][1] = __float_as_uint(Wh[kB + 4*136 + nb + nt*8]);
        bl[nt][0] = __float_as_uint(Wl[kB + nb + nt*8]);
        bl[nt][1] = __float_as_uint(Wl[kB + 4*136 + nb + nt*8]);
      }
      #pragma unroll
      for(int mt=0; mt<2; mt++)
        #pragma unroll
        for(int nt=0; nt<8; nt++){
          mma_tf32(acc[mt][nt], ah[mt], bh[nt]);
          mma_tf32(acc[mt][nt], ah[mt], bl[nt]);
          mma_tf32(acc[mt][nt], al[mt], bh[nt]);
        }
    }

    if(s+1 < nStages){
      SSTORE((s+1)&1);
      __syncthreads();
    }
  }

  #pragma unroll
  for(int mt=0; mt<2; mt++){
    int r0 = row0 + wm*32 + mt*16 + (lane >> 2);
    #pragma unroll
    for(int nt=0; nt<8; nt++){
      int c = col0 + wn*64 + nt*8 + (lane & 3)*2;
      if(c < N){
        float2 bs = *(const float2*)&bias[c];
        float2 o0; o0.x = acc[mt][nt][0] + bs.x; o0.y = acc[mt][nt][1] + bs.y;
        *(float2*)&C[(size_t)r0*N + c] = o0;
        float2 o1; o1.x = acc[mt][nt][2] + bs.x; o1.y = acc[mt][nt][3] + bs.y;
        *(float2*)&C[(size_t)(r0+8)*N + c] = o1;
      }
    }
  }
  #undef GLOAD
  #undef SSTORE
}

// =====================================================================
// QK^T scores, 3xTF32, NT. Both operands m-major stride-20 (round-5
// proven conflict-free fragment pattern). K=128. Fused 1/sqrt(128).
// =====================================================================
#define QK_ASZ 2560                 // 128*20
#define QK_SMEM (4*2*QK_ASZ*4)      // 81920

__global__ __launch_bounds__(256) void qk_scores_tf32(
    const float* __restrict__ q, const float* __restrict__ k,
    float* __restrict__ scores)
{
  extern __shared__ float smq[];
  float* Qhi = smq;                  // [2][QK_ASZ]
  float* Qlo = Qhi + 2*QK_ASZ;
  float* Khi = Qlo + 2*QK_ASZ;
  float* Klo = Khi + 2*QK_ASZ;

  int bh = blockIdx.z;
  int b = bh / Hh, h = bh - b*Hh;
  const float* Ag = q + (size_t)b*Ll*DIN + (size_t)h*128;
  const float* Bg = k + (size_t)b*Ll*DIN + (size_t)h*128;

  int tid = threadIdx.x, lane = tid & 31, wid = tid >> 5;
  int wm = wid & 3, wn = wid >> 2;
  int row0 = blockIdx.y*128, col0 = blockIdx.x*128;
  const int nStages = 8;  // K=128

  float acc[2][8][4];
  #pragma unroll
  for(int i=0;i<2;i++)
    #pragma unroll
    for(int j=0;j<8;j++)
      #pragma unroll
      for(int t=0;t<4;t++) acc[i][j][t] = 0.f;

  float4 pa[2], pb[2];

  #define QGLOAD(k0)                                                        \
    {                                                                       \
      _Pragma("unroll")                                                     \
      for(int i=0;i<2;i++){                                                 \
        int f = tid + i*256; int m = f>>2, kq = f&3;                        \
        pa[i] = *(const float4*)&Ag[(size_t)(row0+m)*DIN + (k0) + kq*4];    \
        pb[i] = *(const float4*)&Bg[(size_t)(col0+m)*DIN + (k0) + kq*4];    \
      }                                                                     \
    }

  #define QSSTORE(p)                                                        \
    {                                                                       \
      _Pragma("unroll")                                                     \
      for(int i=0;i<2;i++){                                                 \
        int f = tid + i*256; int m = f>>2, kq = f&3;                        \
        float4 h, l;                                                        \
        cvt_hilo(pa[i].x, h.x, l.x); cvt_hilo(pa[i].y, h.y, l.y);           \
        cvt_hilo(pa[i].z, h.z, l.z); cvt_hilo(pa[i].w, h.w, l.w);           \
        *(float4*)&Qhi[(p)*QK_ASZ + m*20 + kq*4] = h;                       \
        *(float4*)&Qlo[(p)*QK_ASZ + m*20 + kq*4] = l;                       \
        cvt_hilo(pb[i].x, h.x, l.x); cvt_hilo(pb[i].y, h.y, l.y);           \
        cvt_hilo(pb[i].z, h.z, l.z); cvt_hilo(pb[i].w, h.w, l.w);           \
        *(float4*)&Khi[(p)*QK_ASZ + m*20 + kq*4] = h;                       \
        *(float4*)&Klo[(p)*QK_ASZ + m*20 + kq*4] = l;                       \
      }                                                                     \
    }

  QGLOAD(0);
  QSSTORE(0);
  __syncthreads();

  for(int s=0; s<nStages; s++){
    int p = s & 1;
    if(s+1 < nStages) QGLOAD((s+1)*16);

    const float* Ah = Qhi + p*QK_ASZ;
    const float* Al = Qlo + p*QK_ASZ;
    const float* Bh = Khi + p*QK_ASZ;
    const float* Blp = Klo + p*QK_ASZ;

    #pragma unroll
    for(int k8=0; k8<16; k8+=8){
      int kA = k8 + (lane & 3);
      int mb = wm*32 + (lane >> 2);
      unsigned ah[2][4], al[2][4];
      #pragma unroll
      for(int mt=0; mt<2; mt++){
        int m0 = (mb + mt*16)*20;
        ah[mt][0] = __float_as_uint(Ah[m0 + kA]);
        ah[mt][1] = __float_as_uint(Ah[m0 + 160 + kA]);
        ah[mt][2] = __float_as_uint(Ah[m0 + kA + 4]);
        ah[mt][3] = __float_as_uint(Ah[m0 + 160 + kA + 4]);
        al[mt][0] = __float_as_uint(Al[m0 + kA]);
        al[mt][1] = __float_as_uint(Al[m0 + 160 + kA]);
        al[mt][2] = __float_as_uint(Al[m0 + kA + 4]);
        al[mt][3] = __float_as_uint(Al[m0 + 160 + kA + 4]);
      }
      int nbase = wn*64 + (lane >> 2);
      unsigned bhf[8][2], blf[8][2];
      #pragma unroll
      for(int nt=0; nt<8; nt++){
        int n0 = (nbase + nt*8)*20;
        bhf[nt][0] = __float_as_uint(Bh[n0 + kA]);
        bhf[nt][1] = __float_as_uint(Bh[n0 + kA + 4]);
        blf[nt][0] = __float_as_uint(Blp[n0 + kA]);
        blf[nt][1] = __float_as_uint(Blp[n0 + kA + 4]);
      }
      #pragma unroll
      for(int mt=0; mt<2; mt++)
        #pragma unroll
        for(int nt=0; nt<8; nt++){
          mma_tf32(acc[mt][nt], ah[mt], bhf[nt]);
          mma_tf32(acc[mt][nt], ah[mt], blf[nt]);
          mma_tf32(acc[mt][nt], al[mt], bhf[nt]);
        }
    }

    if(s+1 < nStages){
      QSSTORE((s+1)&1);
      __syncthreads();
    }
  }

  const float scale = 0.08838834764831845f; // 1/sqrt(128)
  #pragma unroll
  for(int mt=0; mt<2; mt++){
    int r0 = row0 + wm*32 + mt*16 + (lane >> 2);
    #pragma unroll
    for(int nt=0; nt<8; nt++){
      int c = col0 + wn*64 + nt*8 + (lane & 3)*2;
      float2 o0; o0.x = acc[mt][nt][0]*scale; o0.y = acc[mt][nt][1]*scale;
      *(float2*)&scores[((size_t)bh*Ll + r0)*Ll + c] = o0;
      float2 o1; o1.x = acc[mt][nt][2]*scale; o1.y = acc[mt][nt][3]*scale;
      *(float2*)&scores[((size_t)bh*Ll + r0 + 8)*Ll + c] = o1;
    }
  }
  #undef QGLOAD
  #undef QSSTORE
}

// ---------------- softmax over m per (b,l), all 6 heads batched ----------------
__global__ __launch_bounds__(256) void softmax_mean_kernel(
    const float* __restrict__ scores, float* __restrict__ pattn)
{
  __shared__ float red1[Hh][8];
  __shared__ float r1[Hh];
  __shared__ float red2[Hh][8];
  __shared__ float r2[Hh];
  int bl = blockIdx.x;
  int b = bl >> 8, l = bl & 255;
  int m = threadIdx.x, w = m >> 5, lane = m & 31;
  const float* base = scores + ((size_t)(b*Hh)*Ll + l)*Ll + m;
  float s[Hh];
  #pragma unroll
  for(int h=0;h<Hh;h++) s[h] = base[(size_t)h*Ll*Ll];

  float v[Hh];
  #pragma unroll
  for(int h=0;h<Hh;h++){
    v[h] = s[h];
    #pragma unroll
    for(int o=16;o;o>>=1) v[h] = fmaxf(v[h], __shfl_xor_sync(0xffffffffu, v[h], o));
  }
  if(lane == 0){
    #pragma unroll
    for(int h=0;h<Hh;h++) red1[h][w] = v[h];
  }
  __syncthreads();
  if(m < Hh){
    float x = red1[m][0];
    #pragma unroll
    for(int j=1;j<8;j++) x = fmaxf(x, red1[m][j]);
    r1[m] = x;
  }
  __syncthreads();

  float e[Hh];
  #pragma unroll
  for(int h=0;h<Hh;h++){
    e[h] = expf(s[h] - r1[h]);
    v[h] = e[h];
    #pragma unroll
    for(int o=16;o;o>>=1) v[h] += __shfl_xor_sync(0xffffffffu, v[h], o);
  }
  if(lane == 0){
    #pragma unroll
    for(int h=0;h<Hh;h++) red2[h][w] = v[h];
  }
  __syncthreads();
  if(m < Hh){
    float x = red2[m][0];
    #pragma unroll
    for(int j=1;j<8;j++) x += red2[m][j];
    r2[m] = x;
  }
  __syncthreads();

  float acc = 0.f;
  #pragma unroll
  for(int h=0;h<Hh;h++) acc += e[h] / r2[h];
  pattn[(size_t)bl*Ll + m] = acc * (1.f/6.f);
}

// ---------------- exact 1024th-largest per batch via radix select ----------------
__global__ __launch_bounds__(1024) void topk_select_kernel(
    const float* __restrict__ pattn, float* __restrict__ kth)
{
  int b = blockIdx.x;
  int tid = threadIdx.x;
  const unsigned* v = (const unsigned*)(pattn + (size_t)b*Ll*Ll);
  __shared__ unsigned hist[256];
  __shared__ unsigned s_prefix;
  __shared__ int s_k;
  if(tid == 0){ s_prefix = 0u; s_k = TOPK; }
  __syncthreads();
  for(int pass=3; pass>=0; --pass){
    int shift = pass*8;
    if(tid < 256) hist[tid] = 0u;
    __syncthreads();
    unsigned prefix = s_prefix;
    unsigned mask = (pass==3) ? 0u : (0xFFFFFFFFu << ((pass+1)*8));
    for(int i=tid; i<Ll*Ll; i+=1024){
      unsigned x = v[i];
      if((x & mask) == prefix) atomicAdd(&hist[(x >> shift) & 0xFF], 1u);
    }
    __syncthreads();
    if(tid == 0){
      int k = s_k, cum = 0;
      unsigned byte = 0;
      for(int bb=255; bb>=0; --bb){
        int c = (int)hist[bb];
        if(cum + c >= k){ byte = (unsigned)bb; s_k = k - cum; break; }
        cum += c;
      }
      s_prefix = prefix | (byte << shift);
    }
    __syncthreads();
  }
  if(tid == 0) kth[b] = __uint_as_float(s_prefix);
}

// ---------------- adjacency mask (tiled, coalesced transpose) ----------------
// block = (i-tile of 32 rows, batch). Loads row tile + padded column tile
// through smem; all global accesses coalesced.
__global__ __launch_bounds__(256) void build_adj_tiled(
    const float* __restrict__ pattn, const float* __restrict__ kth,
    unsigned char* __restrict__ adj)
{
  extern __shared__ float smadj[];
  float* Pi = smadj;          // [32][256]
  float* Tj = Pi + 32*256;    // [256][33]

  int b = blockIdx.y, it = blockIdx.x;
  int i0 = it*32;
  int tid = threadIdx.x, w = tid >> 5, lane = tid & 31;
  const float* p = pattn + (size_t)b*Ll*Ll;

  // row tile: rows i0..i0+31, all 256 cols (coalesced)
  #pragma unroll
  for(int rr=0; rr<4; rr++){
    int r = w*4 + rr;
    #pragma unroll
    for(int cc=0; cc<8; cc++){
      int c = lane + cc*32;
      Pi[r*256 + c] = p[(size_t)(i0+r)*Ll + c];
    }
  }
  // column tile: all 256 rows, cols i0..i0+31 (each warp-row read = 128B contiguous)
  #pragma unroll
  for(int jj=0; jj<32; jj++){
    int j = w*32 + jj;
    Tj[j*33 + lane] = p[(size_t)j*Ll + i0 + lane];
  }
  __syncthreads();

  float t = kth[b];
  unsigned char* arow = adj + (size_t)b*Ll*Ll;
  #pragma unroll 4
  for(int ii=0; ii<32; ii++){
    int i = i0 + ii, j = tid;
    bool e = (i==j) || (Pi[ii*256 + j] >= t) || (Tj[j*33 + ii] >= t);
    arow[(size_t)i*Ll + j] = e ? 1 : 0;
  }
}
#define ADJ_SMEM ((32*256 + 256*33)*4)  // 66560

// ---------------- repack Wh(layer,h,d,k) -> Wcat(layer, d, h*50+k) ----------------
__global__ void repack_wh_kernel(const float* __restrict__ Wh, float* __restrict__ wcat){
  int idx = blockIdx.x*blockDim.x + threadIdx.x;
  if(idx >= NLAYERS*Hh*MEMD*DKk) return;
  int layer = idx / (Hh*MEMD*DKk);
  int r = idx - layer*(Hh*MEMD*DKk);
  int h = r / (MEMD*DKk);
  int r2 = r - h*(MEMD*DKk);
  int d = r2 / DKk;
  int kk = r2 - d*DKk;
  wcat[(size_t)layer*MEMD*MEMD + (size_t)d*MEMD + h*DKk + kk] = Wh[idx];
}

// ---------------- s_i, s_j per (b,h,l) ----------------
__global__ void sisj_kernel(const float* __restrict__ proj, const float* __restrict__ awl,
                            float* __restrict__ si, float* __restrict__ sj)
{
  int idx = blockIdx.x*blockDim.x + threadIdx.x;
  if(idx >= Bb*Hh*Ll) return;
  int b = idx / (Hh*Ll);
  int r = idx - b*(Hh*Ll);
  int h = r / Ll;
  int l = r - h*Ll;
  const float* pr = proj + (((size_t)(b*Ll + l))*Hh + h)*DKk;
  const float* w1 = awl;
  const float* w2 = awl + DKk;
  float a = 0.f, c = 0.f;
  #pragma unroll
  for(int k2=0;k2<DKk;k2++){ float pv = pr[k2]; a = fmaf(pv, w1[k2], a); c = fmaf(pv, w2[k2], c); }
  si[idx] = a; sj[idx] = c;
}

// =====================================================================
// fused GAT attention: block per (b,h,half). Two-phase chunked.
// =====================================================================
__global__ __launch_bounds__(256) void gat_attn_kernel(
    const float* __restrict__ proj, const float* __restrict__ si, const float* __restrict__ sj,
    const unsigned char* __restrict__ adj, const float* __restrict__ abp,
    float* __restrict__ cat)
{
  extern __shared__ float smx[];
  float* projS = smx;
  float* Psm   = projS + Ll*DKk;
  float* sjS   = Psm + 32*Ll;
  float* siS   = sjS + Ll;

  int bhh = blockIdx.x;
  int bh = bhh >> 1, half = bhh & 1;
  int b = bh / Hh, h = bh - b*Hh;
  int tid = threadIdx.x;
  int lane = tid & 31, w = tid >> 5;

  {
    const float* projBase = proj + ((size_t)(b*Ll))*MEMD + h*DKk;
    float2* dst = (float2*)projS;
    for(int e=tid; e<Ll*25; e+=256){
      int m = e / 25, t = e - m*25;
      dst[m*25+t] = ((const float2*)(projBase + (size_t)m*MEMD))[t];
    }
  }
  sjS[tid] = sj[(size_t)bh*Ll + tid];
  if(tid < 128) siS[tid] = si[(size_t)bh*Ll + half*128 + tid];
  __syncthreads();

  float abv = abp[0];
  const unsigned char* adjb = adj + (size_t)b*Ll*Ll;

  for(int c=0; c<4; c++){
    #pragma unroll
    for(int rr=0; rr<4; rr++){
      int pr = w*4 + rr;
      int l = half*128 + c*32 + pr;
      float si_l = siS[c*32 + pr];
      const unsigned char* arow = adjb + (size_t)l*Ll;
      float pv[8]; bool okv[8];
      float mx = -3.0e38f;
      #pragma unroll
      for(int j=0;j<8;j++){
        int m = lane + j*32;
        float sval = si_l + sjS[m] + abv;
        sval = (sval > 0.f) ? sval : 0.2f*sval;
        bool ok = arow[m] != 0;
        okv[j] = ok; pv[j] = sval;
        mx = fmaxf(mx, ok ? sval : -3.0e38f);
      }
      #pragma unroll
      for(int o=16;o;o>>=1) mx = fmaxf(mx, __shfl_xor_sync(0xffffffffu, mx, o));
      float ev[8];
      float s = 0.f;
      #pragma unroll
      for(int j=0;j<8;j++){
        ev[j] = okv[j] ? expf(pv[j] - mx) : 0.f;
        s += ev[j];
      }
      #pragma unroll
      for(int o=16;o;o>>=1) s += __shfl_xor_sync(0xffffffffu, s, o);
      float inv = 1.0f / s;
      #pragma unroll
      for(int j=0;j<8;j++)
        Psm[pr*Ll + lane + j*32] = ev[j] * inv;
    }
    __syncthreads();

    if(lane < 25){
      unsigned long long acc[4] = {0ull,0ull,0ull,0ull};
      const unsigned long long* Vp = (const unsigned long long*)projS;
      #pragma unroll 4
      for(int m=0; m<Ll; m++){
        unsigned long long bv = Vp[m*25 + lane];
        #pragma unroll
        for(int t=0;t<4;t++){
          float pt = Psm[(w + 8*t)*Ll + m];
          FFMA2(acc[t], dup_f32(pt), bv);
        }
      }
      #pragma unroll
      for(int t=0;t<4;t++){
        int pr = w + 8*t;
        int l = half*128 + c*32 + pr;
        float2 o = unpack2(acc[t]);
        *(float2*)&cat[((size_t)(b*Ll + l))*MEMD + h*DKk + lane*2] = o;
      }
    }
    __syncthreads();
  }
}

// ---------------- res = h + cat; LayerNorm -> h (in place) ----------------
__global__ __launch_bounds__(256) void add_ln_kernel(
    float* __restrict__ hbuf, const float* __restrict__ cat,
    const float* __restrict__ g, const float* __restrict__ bln)
{
  __shared__ float rbuf[MEMD];
  __shared__ float red[8];
  int row = blockIdx.x, tid = threadIdx.x;
  float s = 0.f;
  for(int d=tid; d<MEMD; d+=256){
    float r = hbuf[(size_t)row*MEMD + d] + cat[(size_t)row*MEMD + d];
    rbuf[d] = r; s += r;
  }
  s = blockSum256(s, red);
  float mu = s * (1.f/MEMD);
  float v = 0.f;
  for(int d=tid; d<MEMD; d+=256){ float r = rbuf[d] - mu; v = fmaf(r, r, v); }
  v = blockSum256(v, red);
  float inv = 1.0f / sqrtf(v*(1.f/MEMD) + 1e-5f);
  for(int d=tid; d<MEMD; d+=256)
    hbuf[(size_t)row*MEMD + d] = (rbuf[d] - mu) * inv * g[d] + bln[d];
}

// ---------------- pool partials: grid (8 chunks, 64 b) ----------------
__global__ __launch_bounds__(256) void pool_part_kernel(
    const float* __restrict__ hbuf, float* __restrict__ part)
{
  int b = blockIdx.y, c = blockIdx.x;
  int tid = threadIdx.x;
  const float* base = hbuf + ((size_t)(b*Ll + c*32))*MEMD;
  for(int d=tid; d<MEMD; d+=256){
    float s = 0.f;
    #pragma unroll 4
    for(int l=0; l<32; l++) s += base[(size_t)l*MEMD + d];
    part[((size_t)(b*8 + c))*MEMD + d] = s;
  }
}

// ---------------- final: pooled = sum(parts)/L; out = pooled @ Wc + bc ----------------
__global__ __launch_bounds__(256) void pool_classify_kernel(
    const float* __restrict__ part, const float* __restrict__ Wc,
    const float* __restrict__ bc, float* __restrict__ out)
{
  __shared__ float pooled[MEMD];
  __shared__ float red[8];
  int b = blockIdx.x, tid = threadIdx.x;
  for(int d=tid; d<MEMD; d+=256){
    float s = 0.f;
    #pragma unroll
    for(int c=0; c<8; c++) s += part[((size_t)(b*8 + c))*MEMD + d];
    pooled[d] = s * (1.f/Ll);
  }
  __syncthreads();
  for(int c=0; c<NCc; c++){
    float p = 0.f;
    for(int d=tid; d<MEMD; d+=256) p = fmaf(pooled[d], Wc[d*NCc + c], p);
    p = blockSum256(p, red);
    if(tid == 0) out[b*NCc + c] = p + bc[c];
  }
}

// ---------------- launcher ----------------
extern "C" void kernel_launch(void* const* d_in, const int* in_sizes, int n_in,
                              void* d_out, int out_size)
{
  const float* x    = (const float*)d_in[0];
  const float* wq   = (const float*)d_in[1];
  const float* bq   = (const float*)d_in[2];
  const float* wk   = (const float*)d_in[3];
  const float* bk   = (const float*)d_in[4];
  const float* w_in = (const float*)d_in[5];
  const float* b_in = (const float*)d_in[6];
  const float* Wh   = (const float*)d_in[7];
  const float* bh   = (const float*)d_in[8];
  const float* aw   = (const float*)d_in[9];
  const float* ab   = (const float*)d_in[10];
  const float* g_ln = (const float*)d_in[11];
  const float* b_ln = (const float*)d_in[12];
  const float* Wc   = (const float*)d_in[13];
  const float* bc   = (const float*)d_in[14];
  float* out = (float*)d_out;

  float *pq, *pk, *pscores, *ppattn, *pkth, *ph, *pproj, *pcat, *psi, *psj, *pwcat, *ppool;
  unsigned char* padj;
  cudaGetSymbolAddress((void**)&pq, g_q);
  cudaGetSymbolAddress((void**)&pk, g_k);
  cudaGetSymbolAddress((void**)&pscores, g_scores);
  cudaGetSymbolAddress((void**)&ppattn, g_pattn);
  cudaGetSymbolAddress((void**)&pkth, g_kth);
  cudaGetSymbolAddress((void**)&padj, g_adj);
  cudaGetSymbolAddress((void**)&ph, g_h);
  cudaGetSymbolAddress((void**)&pproj, g_proj);
  cudaGetSymbolAddress((void**)&pcat, g_cat);
  cudaGetSymbolAddress((void**)&psi, g_si);
  cudaGetSymbolAddress((void**)&psj, g_sj);
  cudaGetSymbolAddress((void**)&pwcat, g_wcat);
  cudaGetSymbolAddress((void**)&ppool, g_poolpart);

  const int ATTN_SMEM = (Ll*DKk + 32*Ll + Ll + 128) * 4; // 85504 bytes
  cudaFuncSetAttribute(gat_attn_kernel, cudaFuncAttributeMaxDynamicSharedMemorySize, ATTN_SMEM);
  cudaFuncSetAttribute(gemm_tf32x3, cudaFuncAttributeMaxDynamicSharedMemorySize, GEMM_SMEM);
  cudaFuncSetAttribute(qk_scores_tf32, cudaFuncAttributeMaxDynamicSharedMemorySize, QK_SMEM);
  cudaFuncSetAttribute(build_adj_tiled, cudaFuncAttributeMaxDynamicSharedMemorySize, ADJ_SMEM);

  // q, k projections (3xTF32 tensor core)
  gemm_tf32x3<<<dim3(DIN/128, BL/128), 256, GEMM_SMEM>>>(x, wq, bq, pq, BL, DIN, DIN);
  gemm_tf32x3<<<dim3(DIN/128, BL/128), 256, GEMM_SMEM>>>(x, wk, bk, pk, BL, DIN, DIN);

  // scores (3xTF32) + softmax + head-mean
  qk_scores_tf32<<<dim3(2, 2, Bb*Hh), 256, QK_SMEM>>>(pq, pk, pscores);
  softmax_mean_kernel<<<Bb*Ll, 256>>>(pscores, ppattn);

  // top-k threshold + adjacency
  topk_select_kernel<<<Bb, 1024>>>(ppattn, pkth);
  build_adj_tiled<<<dim3(8, Bb), 256, ADJ_SMEM>>>(ppattn, pkth, padj);

  // h = x @ w_in + b_in (3xTF32)
  gemm_tf32x3<<<dim3((MEMD+127)/128, BL/128), 256, GEMM_SMEM>>>(x, w_in, b_in, ph, BL, MEMD, DIN);

  // repack Wh into (layer, MEM, H*DK)
  repack_wh_kernel<<<(NLAYERS*Hh*MEMD*DKk + 255)/256, 256>>>(Wh, pwcat);

  for(int layer=0; layer<NLAYERS; layer++){
    gemm_tf32x3<<<dim3((MEMD+127)/128, BL/128), 256, GEMM_SMEM>>>(
        ph, pwcat + (size_t)layer*MEMD*MEMD, bh + layer*MEMD, pproj, BL, MEMD, MEMD);
    sisj_kernel<<<(Bb*Hh*Ll + 127)/128, 128>>>(pproj, aw + layer*2*DKk, psi, psj);
    gat_attn_kernel<<<Bb*Hh*2, 256, ATTN_SMEM>>>(pproj, psi, psj, padj, ab + layer, pcat);
    add_ln_kernel<<<Bb*Ll, 256>>>(ph, pcat, g_ln + layer*MEMD, b_ln + layer*MEMD);
  }

  pool_part_kernel<<<dim3(8, Bb), 256>>>(ph, ppool);
  pool_classify_kernel<<<Bb, 256>>>(ppool, Wc, bc, out);
}